// round 1
// baseline (speedup 1.0000x reference)
#include <cuda_runtime.h>
#include <cuda_bf16.h>
#include <cstdint>
#include <cstddef>

// Problem constants
#define S_LEN 2048
#define B_SZ  2
#define D_MODEL 512
#define H_HEADS 8
#define DK 64
#define F_FFN 2048
#define M_ROWS (B_SZ * S_LEN)          // 4096
#define OUT_ELEMS (S_LEN * B_SZ * D_MODEL) // 2097152

// Scratch layout (floats)
#define OFF_X   0
#define OFF_Q   (1 * 2097152)
#define OFF_K   (2 * 2097152)
#define OFF_V   (3 * 2097152)
#define OFF_AO  (4 * 2097152)
#define OFF_T1  (5 * 2097152)
#define OFF_H   (6 * 2097152)
#define OFF_FF  (7 * 2097152)
#define SCRATCH_FLOATS (7 * 2097152 + 8388608)

__device__ float g_scratch[SCRATCH_FLOATS];

// ---------------------------------------------------------------------------
// Packed f32x2 helpers (Blackwell fma.rn.f32x2)
// ---------------------------------------------------------------------------
__device__ __forceinline__ unsigned long long pack2(float x, float y) {
    unsigned long long r;
    asm("mov.b64 %0, {%1, %2};" : "=l"(r) : "f"(x), "f"(y));
    return r;
}
__device__ __forceinline__ void unpack2(unsigned long long p, float& x, float& y) {
    asm("mov.b64 {%0, %1}, %2;" : "=f"(x), "=f"(y) : "l"(p));
}
__device__ __forceinline__ void ffma2p(unsigned long long& c, unsigned long long a2,
                                       unsigned long long b2) {
    asm("fma.rn.f32x2 %0, %1, %2, %0;" : "+l"(c) : "l"(a2), "l"(b2));
}

// ---------------------------------------------------------------------------
// Transpose (S,B,D) -> (B,S,D)
// ---------------------------------------------------------------------------
__global__ void __launch_bounds__(128) transpose_src(const float* __restrict__ src,
                                                     float* __restrict__ x) {
    int id = blockIdx.x;            // id = s*B + b
    int s = id >> 1;
    int b = id & 1;
    const float4* in = (const float4*)(src + (size_t)id * D_MODEL);
    float4* out = (float4*)(x + ((size_t)(b * S_LEN + s)) * D_MODEL);
    out[threadIdx.x] = in[threadIdx.x];
}

// ---------------------------------------------------------------------------
// Generic NT GEMM: C[m,n] = sum_k A[m,k] * Bw[n,k]  (+ epilogue)
// BM=128, BN=128, BK=8, 256 threads, thread tile 8x8 (as 8x4 f32x2)
// EPI: 0 = QKV head-scatter, 1 = + resid, 2 = + bias, relu, 3 = + bias + resid
// ---------------------------------------------------------------------------
template <int EPI>
__global__ void __launch_bounds__(256) gemm_nt(
    const float* __restrict__ A, const float* __restrict__ Bw,
    float* __restrict__ C, int N, int K,
    const float* __restrict__ bias, const float* __restrict__ resid) {
    __shared__ __align__(16) float As[8 * 128];
    __shared__ __align__(16) float Bs[8 * 128];

    int t = threadIdx.x;
    int m0 = blockIdx.y * 128;
    int n0 = blockIdx.x * 128;

    int lr = t >> 1;            // 0..127 (row within tile)
    int lq = (t & 1) * 4;       // 0 or 4 (k-quad)
    const float* Aload = A + (size_t)(m0 + lr) * K + lq;
    const float* Bload = Bw + (size_t)(n0 + lr) * K + lq;

    int ty = t >> 4;            // 0..15
    int tx = t & 15;            // 0..15

    unsigned long long acc[8][4];
#pragma unroll
    for (int i = 0; i < 8; i++)
#pragma unroll
        for (int j = 0; j < 4; j++) acc[i][j] = 0ull;

    for (int k0 = 0; k0 < K; k0 += 8) {
        float4 av = *(const float4*)(Aload + k0);
        float4 bv = *(const float4*)(Bload + k0);
        __syncthreads();
        As[(lq + 0) * 128 + lr] = av.x;
        As[(lq + 1) * 128 + lr] = av.y;
        As[(lq + 2) * 128 + lr] = av.z;
        As[(lq + 3) * 128 + lr] = av.w;
        Bs[(lq + 0) * 128 + lr] = bv.x;
        Bs[(lq + 1) * 128 + lr] = bv.y;
        Bs[(lq + 2) * 128 + lr] = bv.z;
        Bs[(lq + 3) * 128 + lr] = bv.w;
        __syncthreads();
#pragma unroll
        for (int kk = 0; kk < 8; kk++) {
            unsigned long long a2[8];
#pragma unroll
            for (int i = 0; i < 8; i++) {
                float avv = As[kk * 128 + ty * 8 + i];
                a2[i] = pack2(avv, avv);
            }
            unsigned long long b2[4];
            const unsigned long long* bp =
                (const unsigned long long*)(Bs + kk * 128) + tx * 4;
#pragma unroll
            for (int j = 0; j < 4; j++) b2[j] = bp[j];
#pragma unroll
            for (int i = 0; i < 8; i++)
#pragma unroll
                for (int j = 0; j < 4; j++) ffma2p(acc[i][j], a2[i], b2[j]);
        }
    }

#pragma unroll
    for (int i = 0; i < 8; i++) {
        int m = m0 + ty * 8 + i;
#pragma unroll
        for (int j = 0; j < 4; j++) {
            int n = n0 + tx * 8 + j * 2;
            float v0, v1;
            unpack2(acc[i][j], v0, v1);
            if (EPI == 0) {
                // scatter to (b, h, s, dk) head layout: N == 512
                int b = m >> 11;            // /S_LEN
                int s = m & (S_LEN - 1);
                int h = n >> 6;
                int d0 = n & 63;
                float* dst = C + ((size_t)((b * H_HEADS + h) * S_LEN + s)) * DK + d0;
                dst[0] = v0;
                dst[1] = v1;
            } else if (EPI == 1) {
                size_t o = (size_t)m * N + n;
                float2 r = *(const float2*)(resid + o);
                *(float2*)(C + o) = make_float2(v0 + r.x, v1 + r.y);
            } else if (EPI == 2) {
                size_t o = (size_t)m * N + n;
                *(float2*)(C + o) = make_float2(fmaxf(v0 + bias[n], 0.f),
                                                fmaxf(v1 + bias[n + 1], 0.f));
            } else {
                size_t o = (size_t)m * N + n;
                float2 r = *(const float2*)(resid + o);
                *(float2*)(C + o) = make_float2(v0 + bias[n] + r.x,
                                                v1 + bias[n + 1] + r.y);
            }
        }
    }
}

// ---------------------------------------------------------------------------
// Attention: one block per (b,h, 16-query tile).
// smem: scores 16x2048, q 16x64, K/V staging 64x65 (pad).
// Writes full softmax matrix p_attn and attention output o.
// ---------------------------------------------------------------------------
#define ATTN_SMEM_FLOATS (16 * 2048 + 16 * 64 + 64 * 65)
#define ATTN_SMEM_BYTES (ATTN_SMEM_FLOATS * 4)

__global__ void __launch_bounds__(256) attn_kernel(
    const float* __restrict__ q, const float* __restrict__ k,
    const float* __restrict__ v, const float* __restrict__ sph,
    float* __restrict__ p_out, float* __restrict__ o_out) {
    extern __shared__ float sm[];
    float* sc = sm;                      // 16 * 2048
    float* qs = sm + 16 * 2048;          // 16 * 64
    float* kt = qs + 16 * 64;            // 64 * 65

    int t = threadIdx.x;
    int bh = blockIdx.y;                 // 0..15
    int q0 = blockIdx.x * 16;

    // load q tile (contiguous)
    const size_t qoff = ((size_t)bh * S_LEN + q0) * DK;
    for (int i = t; i < 16 * DK; i += 256) qs[i] = q[qoff + i];

    int r = t >> 4;                      // query row within tile 0..15
    int c4 = (t & 15) << 2;              // key-col group base 0..60

    const float* kbh = k + (size_t)bh * S_LEN * DK;
    const float* sprow = sph + ((size_t)bh * S_LEN + q0 + r) * S_LEN;

    // -------- scores --------
    for (int kt0 = 0; kt0 < S_LEN; kt0 += 64) {
        __syncthreads();
        const float* kb = kbh + (size_t)kt0 * DK;
#pragma unroll
        for (int i = 0; i < 4; i++) {
            int idx4 = t + i * 256;      // 0..1023 float4s
            int row = idx4 >> 4;
            int col = (idx4 & 15) << 2;
            float4 w = *(const float4*)(kb + row * 64 + col);
            float* d = kt + row * 65 + col;
            d[0] = w.x; d[1] = w.y; d[2] = w.z; d[3] = w.w;
        }
        __syncthreads();
        float a0 = 0.f, a1 = 0.f, a2 = 0.f, a3 = 0.f;
        const float* qr = qs + r * 64;
        const float* k0p = kt + (c4 + 0) * 65;
        const float* k1p = kt + (c4 + 1) * 65;
        const float* k2p = kt + (c4 + 2) * 65;
        const float* k3p = kt + (c4 + 3) * 65;
#pragma unroll 16
        for (int d = 0; d < 64; d++) {
            float qv = qr[d];
            a0 += qv * k0p[d];
            a1 += qv * k1p[d];
            a2 += qv * k2p[d];
            a3 += qv * k3p[d];
        }
        float4 sp = *(const float4*)(sprow + kt0 + c4);
        float* so = sc + r * S_LEN + kt0 + c4;
        so[0] = a0 * 0.125f * sp.x;
        so[1] = a1 * 0.125f * sp.y;
        so[2] = a2 * 0.125f * sp.z;
        so[3] = a3 * 0.125f * sp.w;
    }
    __syncthreads();

    // -------- softmax (8 warps, 2 rows each) --------
    int warp = t >> 5, lane = t & 31;
    for (int rr = warp; rr < 16; rr += 8) {
        float4* row4 = (float4*)(sc + rr * S_LEN);
        float mx = -1e30f;
#pragma unroll 4
        for (int i = lane; i < 512; i += 32) {
            float4 x4 = row4[i];
            mx = fmaxf(mx, fmaxf(fmaxf(x4.x, x4.y), fmaxf(x4.z, x4.w)));
        }
#pragma unroll
        for (int o = 16; o; o >>= 1) mx = fmaxf(mx, __shfl_xor_sync(0xffffffffu, mx, o));
        float sum = 0.f;
#pragma unroll 4
        for (int i = lane; i < 512; i += 32) {
            float4 x4 = row4[i];
            x4.x = __expf(x4.x - mx);
            x4.y = __expf(x4.y - mx);
            x4.z = __expf(x4.z - mx);
            x4.w = __expf(x4.w - mx);
            row4[i] = x4;
            sum += x4.x + x4.y + x4.z + x4.w;
        }
#pragma unroll
        for (int o = 16; o; o >>= 1) sum += __shfl_xor_sync(0xffffffffu, sum, o);
        float inv = 1.0f / sum;
        float4* pd = (float4*)(p_out + ((size_t)bh * S_LEN + q0 + rr) * S_LEN);
#pragma unroll 4
        for (int i = lane; i < 512; i += 32) {
            float4 x4 = row4[i];
            x4.x *= inv; x4.y *= inv; x4.z *= inv; x4.w *= inv;
            row4[i] = x4;
            pd[i] = x4;
        }
    }

    // -------- PV --------
    const float* vbh = v + (size_t)bh * S_LEN * DK;
    float o0 = 0.f, o1 = 0.f, o2 = 0.f, o3 = 0.f;
    const float* prow = sc + r * S_LEN;
    for (int kt0 = 0; kt0 < S_LEN; kt0 += 64) {
        __syncthreads();
        const float* vb = vbh + (size_t)kt0 * DK;
#pragma unroll
        for (int i = 0; i < 4; i++) {
            int idx4 = t + i * 256;
            int row = idx4 >> 4;
            int col = (idx4 & 15) << 2;
            float4 w = *(const float4*)(vb + row * 64 + col);
            float* d = kt + row * 65 + col;
            d[0] = w.x; d[1] = w.y; d[2] = w.z; d[3] = w.w;
        }
        __syncthreads();
#pragma unroll 8
        for (int kk = 0; kk < 64; kk++) {
            float p = prow[kt0 + kk];
            const float* vr = kt + kk * 65 + c4;
            o0 += p * vr[0];
            o1 += p * vr[1];
            o2 += p * vr[2];
            o3 += p * vr[3];
        }
    }
    int b = bh >> 3, h = bh & 7;
    float* od = o_out + ((size_t)(b * S_LEN + q0 + r)) * D_MODEL + h * DK + c4;
    od[0] = o0; od[1] = o1; od[2] = o2; od[3] = o3;
}

// ---------------------------------------------------------------------------
// LayerNorm helpers
// ---------------------------------------------------------------------------
__device__ __forceinline__ float blockSum256(float v, float* sred) {
#pragma unroll
    for (int o = 16; o; o >>= 1) v += __shfl_xor_sync(0xffffffffu, v, o);
    __syncthreads();
    if ((threadIdx.x & 31) == 0) sred[threadIdx.x >> 5] = v;
    __syncthreads();
    float s = sred[0];
#pragma unroll
    for (int i = 1; i < 8; i++) s += sred[i];
    return s;
}

// t = LN(tin, eps 1e-6, ga, ba); h = LN(xin + t, eps 1e-5, g1, b1)
__global__ void __launch_bounds__(256) ln_double_kernel(
    const float* __restrict__ tin, const float* __restrict__ xin,
    const float* __restrict__ ga, const float* __restrict__ ba,
    const float* __restrict__ g1w, const float* __restrict__ b1w,
    float* __restrict__ hout) {
    __shared__ float sred[8];
    int m = blockIdx.x, t = threadIdx.x;
    float2 v = ((const float2*)(tin + (size_t)m * D_MODEL))[t];
    float2 xv = ((const float2*)(xin + (size_t)m * D_MODEL))[t];
    float mu = blockSum256(v.x + v.y, sred) * (1.f / 512.f);
    float dx = v.x - mu, dy = v.y - mu;
    float var = blockSum256(dx * dx + dy * dy, sred) * (1.f / 512.f);
    float rs = rsqrtf(var + 1e-6f);
    int d0 = t * 2;
    float u0 = xv.x + dx * rs * ga[d0] + ba[d0];
    float u1 = xv.y + dy * rs * ga[d0 + 1] + ba[d0 + 1];
    mu = blockSum256(u0 + u1, sred) * (1.f / 512.f);
    dx = u0 - mu; dy = u1 - mu;
    var = blockSum256(dx * dx + dy * dy, sred) * (1.f / 512.f);
    rs = rsqrtf(var + 1e-5f);
    float2 hv = make_float2(dx * rs * g1w[d0] + b1w[d0],
                            dy * rs * g1w[d0 + 1] + b1w[d0 + 1]);
    ((float2*)(hout + (size_t)m * D_MODEL))[t] = hv;
}

// out[(s*B+b)*D + d] = LN(tin[m], eps 1e-5, g2, b2), m = b*S+s
__global__ void __launch_bounds__(256) ln_final_kernel(
    const float* __restrict__ tin, const float* __restrict__ g2w,
    const float* __restrict__ b2w, float* __restrict__ out) {
    __shared__ float sred[8];
    int m = blockIdx.x, t = threadIdx.x;
    float2 v = ((const float2*)(tin + (size_t)m * D_MODEL))[t];
    float mu = blockSum256(v.x + v.y, sred) * (1.f / 512.f);
    float dx = v.x - mu, dy = v.y - mu;
    float var = blockSum256(dx * dx + dy * dy, sred) * (1.f / 512.f);
    float rs = rsqrtf(var + 1e-5f);
    int d0 = t * 2;
    int b = m >> 11;
    int s = m & (S_LEN - 1);
    float2 ov = make_float2(dx * rs * g2w[d0] + b2w[d0],
                            dy * rs * g2w[d0 + 1] + b2w[d0 + 1]);
    ((float2*)(out + ((size_t)(s * B_SZ + b)) * D_MODEL))[t] = ov;
}

// ---------------------------------------------------------------------------
// Launch
// ---------------------------------------------------------------------------
extern "C" void kernel_launch(void* const* d_in, const int* in_sizes, int n_in,
                              void* d_out, int out_size) {
    const float* src    = (const float*)d_in[0];
    const float* sph    = (const float*)d_in[1];
    const float* w_qs   = (const float*)d_in[2];
    const float* w_ks   = (const float*)d_in[3];
    const float* w_vs   = (const float*)d_in[4];
    const float* w_fc   = (const float*)d_in[5];
    const float* g_attn = (const float*)d_in[6];
    const float* b_attn = (const float*)d_in[7];
    const float* w1     = (const float*)d_in[8];
    const float* b1     = (const float*)d_in[9];
    const float* w2     = (const float*)d_in[10];
    const float* b2     = (const float*)d_in[11];
    const float* g1w    = (const float*)d_in[12];
    const float* bn1    = (const float*)d_in[13];
    const float* g2w    = (const float*)d_in[14];
    const float* bn2    = (const float*)d_in[15];

    float* out = (float*)d_out;
    float* p_out = out + OUT_ELEMS;

    void* sp = nullptr;
    cudaGetSymbolAddress(&sp, g_scratch);
    float* scr = (float*)sp;
    float* gx  = scr + OFF_X;
    float* gq  = scr + OFF_Q;
    float* gk  = scr + OFF_K;
    float* gv  = scr + OFF_V;
    float* gao = scr + OFF_AO;
    float* gt1 = scr + OFF_T1;
    float* gh  = scr + OFF_H;
    float* gff = scr + OFF_FF;

    cudaFuncSetAttribute(attn_kernel, cudaFuncAttributeMaxDynamicSharedMemorySize,
                         ATTN_SMEM_BYTES);

    // 1. x = transpose(src)
    transpose_src<<<S_LEN * B_SZ, 128>>>(src, gx);

    // 2. QKV projections (head-scatter epilogue)
    dim3 g512(D_MODEL / 128, M_ROWS / 128);   // (4, 32)
    gemm_nt<0><<<g512, 256>>>(gx, w_qs, gq, D_MODEL, D_MODEL, nullptr, nullptr);
    gemm_nt<0><<<g512, 256>>>(gx, w_ks, gk, D_MODEL, D_MODEL, nullptr, nullptr);
    gemm_nt<0><<<g512, 256>>>(gx, w_vs, gv, D_MODEL, D_MODEL, nullptr, nullptr);

    // 3. attention: p_attn + o
    attn_kernel<<<dim3(S_LEN / 16, B_SZ * H_HEADS), 256, ATTN_SMEM_BYTES>>>(
        gq, gk, gv, sph, p_out, gao);

    // 4. fc projection + residual(x)
    gemm_nt<1><<<g512, 256>>>(gao, w_fc, gt1, D_MODEL, D_MODEL, nullptr, gx);

    // 5. LN(attn, 1e-6) then h = LN(x + ., 1e-5)
    ln_double_kernel<<<M_ROWS, 256>>>(gt1, gx, g_attn, b_attn, g1w, bn1, gh);

    // 6. FFN up: relu(h @ w1^T + b1)
    dim3 gffn(F_FFN / 128, M_ROWS / 128);     // (16, 32)
    gemm_nt<2><<<gffn, 256>>>(gh, w1, gff, F_FFN, D_MODEL, b1, nullptr);

    // 7. FFN down + b2 + residual(h)
    gemm_nt<3><<<g512, 256>>>(gff, w2, gt1, D_MODEL, F_FFN, b2, gh);

    // 8. final LN + transposed store
    ln_final_kernel<<<M_ROWS, 256>>>(gt1, g2w, bn2, out);
}

// round 3
// speedup vs baseline: 4.2296x; 4.2296x over previous
#include <cuda_runtime.h>
#include <cstdint>
#include <cstddef>

// ---------------------------------------------------------------------------
// Problem constants
// ---------------------------------------------------------------------------
#define S_LEN 2048
#define B_SZ  2
#define D_MODEL 512
#define H_HEADS 8
#define DK 64
#define F_FFN 2048
#define M_ROWS (B_SZ * S_LEN)              // 4096
#define OUT_ELEMS (S_LEN * B_SZ * D_MODEL) // 2097152

// Scratch layout (floats)
#define OFF_X   0
#define OFF_Q   (1 * 2097152)
#define OFF_K   (2 * 2097152)
#define OFF_VT  (3 * 2097152)
#define OFF_AO  (4 * 2097152)
#define OFF_T1  (5 * 2097152)
#define OFF_H   (6 * 2097152)
#define SCRATCH_FLOATS (6 * 2097152 + 8388608)

__device__ float g_scratch[SCRATCH_FLOATS];

// ---------------------------------------------------------------------------
// PTX helpers
// ---------------------------------------------------------------------------
__device__ __forceinline__ uint32_t smem_to_u32(const void* p) {
    uint32_t a;
    asm("{ .reg .u64 t; cvta.to.shared.u64 t, %1; cvt.u32.u64 %0, t; }"
        : "=r"(a) : "l"(p));
    return a;
}

#define CP_ASYNC16(dst, src) \
    asm volatile("cp.async.ca.shared.global [%0], [%1], 16;\n" \
                 :: "r"(dst), "l"(src))
#define CP_COMMIT() asm volatile("cp.async.commit_group;\n" ::: "memory")
#define CP_WAIT1()  asm volatile("cp.async.wait_group 1;\n" ::: "memory")
#define CP_WAIT0()  asm volatile("cp.async.wait_group 0;\n" ::: "memory")

// m16n8k8 tf32 mma: d += A(16x8 row) * B(8x8 col)
__device__ __forceinline__ void mma_tf32(float (&dd)[4], const uint32_t (&a)[4],
                                         const uint32_t (&b)[2]) {
    asm volatile(
        "mma.sync.aligned.m16n8k8.row.col.f32.tf32.tf32.f32 "
        "{%0,%1,%2,%3}, {%4,%5,%6,%7}, {%8,%9}, {%0,%1,%2,%3};\n"
        : "+f"(dd[0]), "+f"(dd[1]), "+f"(dd[2]), "+f"(dd[3])
        : "r"(a[0]), "r"(a[1]), "r"(a[2]), "r"(a[3]), "r"(b[0]), "r"(b[1]));
}

// ---------------------------------------------------------------------------
// Transpose (S,B,D) -> (B,S,D)
// ---------------------------------------------------------------------------
__global__ void __launch_bounds__(128) transpose_src(const float* __restrict__ src,
                                                     float* __restrict__ x) {
    int id = blockIdx.x;
    int s = id >> 1;
    int b = id & 1;
    const float4* in = (const float4*)(src + (size_t)id * D_MODEL);
    float4* out = (float4*)(x + ((size_t)(b * S_LEN + s)) * D_MODEL);
    out[threadIdx.x] = in[threadIdx.x];
}

// ---------------------------------------------------------------------------
// tf32 mma.sync GEMM: C[m,n] = sum_k A[m,k] * Bw[n,k]  (both K-major), + epilogue
// BM=128, BN template (128/64), BK=16, 256 threads (8 warps: 4m x 2n),
// cp.async double-buffered staging with XOR-swizzled smem.
//
// EPI: 0 = QK head-scatter   1 = V^T scatter   2 = scores (*0.125*sph)
//      3 = PV store to model layout            4 = +resid
//      5 = +bias, relu                         6 = +bias +resid
// ---------------------------------------------------------------------------
template <int EPI, int BN>
__global__ void __launch_bounds__(256) gemm_mma(
    const float* __restrict__ A, int lda, long long aZ,
    const float* __restrict__ Bw, int ldb, long long bZ,
    int K, float* __restrict__ C,
    const float* __restrict__ aux1, const float* __restrict__ aux2, int ldc) {
    constexpr int NT = BN / 16;          // B 8-col tiles per warp
    __shared__ float smA[2][128 * 16];
    __shared__ float smB[2][BN * 16];

    const int tid = threadIdx.x;
    const int w = tid >> 5, lane = tid & 31;
    const int g = lane >> 2, t = lane & 3;
    const int mw = w >> 1, nw = w & 1;
    const int m0 = blockIdx.y * 128, n0 = blockIdx.x * BN;
    const int z = blockIdx.z;
    A += (size_t)z * aZ;
    Bw += (size_t)z * bZ;

    const uint32_t sA = smem_to_u32(smA);
    const uint32_t sB = smem_to_u32(smB);

    float d[2][NT][4];
#pragma unroll
    for (int i = 0; i < 2; i++)
#pragma unroll
        for (int j = 0; j < NT; j++)
#pragma unroll
            for (int r = 0; r < 4; r++) d[i][j][r] = 0.f;

    const int NC = K >> 4;

    auto issue = [&](int kc, int buf) {
        int k0 = kc << 4;
#pragma unroll
        for (int i = 0; i < 2; i++) {
            int id = tid + (i << 8);
            int r = id >> 2, q = id & 3;
            uint32_t dst = sA + ((buf * 2048 + r * 16 + ((q ^ (r & 3)) << 2)) << 2);
            const float* src = A + (size_t)(m0 + r) * lda + k0 + (q << 2);
            CP_ASYNC16(dst, src);
        }
#pragma unroll
        for (int i = 0; i < BN / 64; i++) {
            int id = tid + (i << 8);
            int r = id >> 2, q = id & 3;
            uint32_t dst = sB + ((buf * (BN * 16) + r * 16 + ((q ^ (r & 3)) << 2)) << 2);
            const float* src = Bw + (size_t)(n0 + r) * ldb + k0 + (q << 2);
            CP_ASYNC16(dst, src);
        }
        CP_COMMIT();
    };

    issue(0, 0);
    for (int kc = 0; kc < NC; kc++) {
        int buf = kc & 1;
        if (kc + 1 < NC) {
            issue(kc + 1, buf ^ 1);
            CP_WAIT1();
        } else {
            CP_WAIT0();
        }
        __syncthreads();
        const float* Ab = smA[buf];
        const float* Bb = smB[buf];
#pragma unroll
        for (int ks = 0; ks < 2; ks++) {
            const int c0 = (((2 * ks) ^ (g & 3)) << 2) + t;
            const int c1 = (((2 * ks + 1) ^ (g & 3)) << 2) + t;
            uint32_t a[2][4];
#pragma unroll
            for (int mtw = 0; mtw < 2; mtw++) {
                int row = (mw * 2 + mtw) * 16 + g;
                a[mtw][0] = __float_as_uint(Ab[row * 16 + c0]);
                a[mtw][1] = __float_as_uint(Ab[(row + 8) * 16 + c0]);
                a[mtw][2] = __float_as_uint(Ab[row * 16 + c1]);
                a[mtw][3] = __float_as_uint(Ab[(row + 8) * 16 + c1]);
            }
            uint32_t b[NT][2];
#pragma unroll
            for (int ntw = 0; ntw < NT; ntw++) {
                int nr = (nw * NT + ntw) * 8 + g;
                b[ntw][0] = __float_as_uint(Bb[nr * 16 + c0]);
                b[ntw][1] = __float_as_uint(Bb[nr * 16 + c1]);
            }
#pragma unroll
            for (int mtw = 0; mtw < 2; mtw++)
#pragma unroll
                for (int ntw = 0; ntw < NT; ntw++)
                    mma_tf32(d[mtw][ntw], a[mtw], b[ntw]);
        }
        __syncthreads();
    }

    // ---------------- epilogue ----------------
#pragma unroll
    for (int mtw = 0; mtw < 2; mtw++)
#pragma unroll
        for (int ntw = 0; ntw < NT; ntw++)
#pragma unroll
            for (int half = 0; half < 2; half++) {
                int m = m0 + mw * 32 + mtw * 16 + half * 8 + g;
                int n = n0 + nw * (BN / 2) + ntw * 8 + t * 2;
                float v0 = d[mtw][ntw][half * 2 + 0];
                float v1 = d[mtw][ntw][half * 2 + 1];
                if (EPI == 0) {           // Q/K scatter to (b,h,s,dk)
                    int b = m >> 11, s = m & (S_LEN - 1);
                    int h = n >> 6, dd = n & 63;
                    float* dst = C + (((size_t)((b << 3) + h) * S_LEN + s) << 6) + dd;
                    *(float2*)dst = make_float2(v0, v1);
                } else if (EPI == 1) {    // V^T scatter to (b,h,dk,s)
                    int b = m >> 11, s = m & (S_LEN - 1);
                    int h = n >> 6, dd = n & 63;
                    size_t base = ((size_t)((b << 3) + h) * DK + dd) * S_LEN + s;
                    C[base] = v0;
                    C[base + S_LEN] = v1;
                } else if (EPI == 2) {    // scores: * 0.125 * sph
                    size_t idx = ((size_t)z * S_LEN + m) * S_LEN + n;
                    float2 sp = *(const float2*)(aux1 + idx);
                    *(float2*)(C + idx) = make_float2(v0 * 0.125f * sp.x,
                                                      v1 * 0.125f * sp.y);
                } else if (EPI == 3) {    // PV output -> (b, s, h*64+n)
                    size_t dst = ((size_t)((z >> 3) * S_LEN + m)) * D_MODEL +
                                 (z & 7) * DK + n;
                    *(float2*)(C + dst) = make_float2(v0, v1);
                } else if (EPI == 4) {    // + resid
                    size_t o = (size_t)m * ldc + n;
                    float2 rr = *(const float2*)(aux1 + o);
                    *(float2*)(C + o) = make_float2(v0 + rr.x, v1 + rr.y);
                } else if (EPI == 5) {    // + bias, relu
                    size_t o = (size_t)m * ldc + n;
                    float2 bb = *(const float2*)(aux1 + n);
                    *(float2*)(C + o) = make_float2(fmaxf(v0 + bb.x, 0.f),
                                                    fmaxf(v1 + bb.y, 0.f));
                } else {                  // + bias + resid
                    size_t o = (size_t)m * ldc + n;
                    float2 bb = *(const float2*)(aux1 + n);
                    float2 rr = *(const float2*)(aux2 + o);
                    *(float2*)(C + o) = make_float2(v0 + bb.x + rr.x,
                                                    v1 + bb.y + rr.y);
                }
            }
}

// ---------------------------------------------------------------------------
// Row softmax in place over p (32768 rows x 2048)
// ---------------------------------------------------------------------------
__global__ void __launch_bounds__(256) softmax_rows(float* __restrict__ p) {
    __shared__ float red[8];
    int t = threadIdx.x;
    float4* row = (float4*)(p + (size_t)blockIdx.x * S_LEN);
    float4 a = row[t], b = row[t + 256];
    float mx = fmaxf(fmaxf(fmaxf(a.x, a.y), fmaxf(a.z, a.w)),
                     fmaxf(fmaxf(b.x, b.y), fmaxf(b.z, b.w)));
#pragma unroll
    for (int o = 16; o; o >>= 1) mx = fmaxf(mx, __shfl_xor_sync(0xffffffffu, mx, o));
    if ((t & 31) == 0) red[t >> 5] = mx;
    __syncthreads();
    float gmx = red[0];
#pragma unroll
    for (int i = 1; i < 8; i++) gmx = fmaxf(gmx, red[i]);
    __syncthreads();
    a.x = __expf(a.x - gmx); a.y = __expf(a.y - gmx);
    a.z = __expf(a.z - gmx); a.w = __expf(a.w - gmx);
    b.x = __expf(b.x - gmx); b.y = __expf(b.y - gmx);
    b.z = __expf(b.z - gmx); b.w = __expf(b.w - gmx);
    float ls = a.x + a.y + a.z + a.w + b.x + b.y + b.z + b.w;
#pragma unroll
    for (int o = 16; o; o >>= 1) ls += __shfl_xor_sync(0xffffffffu, ls, o);
    if ((t & 31) == 0) red[t >> 5] = ls;
    __syncthreads();
    float tot = red[0];
#pragma unroll
    for (int i = 1; i < 8; i++) tot += red[i];
    float inv = 1.0f / tot;
    a.x *= inv; a.y *= inv; a.z *= inv; a.w *= inv;
    b.x *= inv; b.y *= inv; b.z *= inv; b.w *= inv;
    row[t] = a;
    row[t + 256] = b;
}

// ---------------------------------------------------------------------------
// LayerNorm kernels
// ---------------------------------------------------------------------------
__device__ __forceinline__ float blockSum256(float v, float* sred) {
#pragma unroll
    for (int o = 16; o; o >>= 1) v += __shfl_xor_sync(0xffffffffu, v, o);
    __syncthreads();
    if ((threadIdx.x & 31) == 0) sred[threadIdx.x >> 5] = v;
    __syncthreads();
    float s = sred[0];
#pragma unroll
    for (int i = 1; i < 8; i++) s += sred[i];
    return s;
}

__global__ void __launch_bounds__(256) ln_double_kernel(
    const float* __restrict__ tin, const float* __restrict__ xin,
    const float* __restrict__ ga, const float* __restrict__ ba,
    const float* __restrict__ g1w, const float* __restrict__ b1w,
    float* __restrict__ hout) {
    __shared__ float sred[8];
    int m = blockIdx.x, t = threadIdx.x;
    float2 v = ((const float2*)(tin + (size_t)m * D_MODEL))[t];
    float2 xv = ((const float2*)(xin + (size_t)m * D_MODEL))[t];
    float mu = blockSum256(v.x + v.y, sred) * (1.f / 512.f);
    float dx = v.x - mu, dy = v.y - mu;
    float var = blockSum256(dx * dx + dy * dy, sred) * (1.f / 512.f);
    float rs = rsqrtf(var + 1e-6f);
    int d0 = t * 2;
    float u0 = xv.x + dx * rs * ga[d0] + ba[d0];
    float u1 = xv.y + dy * rs * ga[d0 + 1] + ba[d0 + 1];
    mu = blockSum256(u0 + u1, sred) * (1.f / 512.f);
    dx = u0 - mu; dy = u1 - mu;
    var = blockSum256(dx * dx + dy * dy, sred) * (1.f / 512.f);
    rs = rsqrtf(var + 1e-5f);
    float2 hv = make_float2(dx * rs * g1w[d0] + b1w[d0],
                            dy * rs * g1w[d0 + 1] + b1w[d0 + 1]);
    ((float2*)(hout + (size_t)m * D_MODEL))[t] = hv;
}

__global__ void __launch_bounds__(256) ln_final_kernel(
    const float* __restrict__ tin, const float* __restrict__ g2w,
    const float* __restrict__ b2w, float* __restrict__ out) {
    __shared__ float sred[8];
    int m = blockIdx.x, t = threadIdx.x;
    float2 v = ((const float2*)(tin + (size_t)m * D_MODEL))[t];
    float mu = blockSum256(v.x + v.y, sred) * (1.f / 512.f);
    float dx = v.x - mu, dy = v.y - mu;
    float var = blockSum256(dx * dx + dy * dy, sred) * (1.f / 512.f);
    float rs = rsqrtf(var + 1e-5f);
    int d0 = t * 2;
    int b = m >> 11;
    int s = m & (S_LEN - 1);
    float2 ov = make_float2(dx * rs * g2w[d0] + b2w[d0],
                            dy * rs * g2w[d0 + 1] + b2w[d0 + 1]);
    ((float2*)(out + ((size_t)(s * B_SZ + b)) * D_MODEL))[t] = ov;
}

// ---------------------------------------------------------------------------
// Launch
// ---------------------------------------------------------------------------
extern "C" void kernel_launch(void* const* d_in, const int* in_sizes, int n_in,
                              void* d_out, int out_size) {
    const float* src    = (const float*)d_in[0];
    const float* sph    = (const float*)d_in[1];
    const float* w_qs   = (const float*)d_in[2];
    const float* w_ks   = (const float*)d_in[3];
    const float* w_vs   = (const float*)d_in[4];
    const float* w_fc   = (const float*)d_in[5];
    const float* g_attn = (const float*)d_in[6];
    const float* b_attn = (const float*)d_in[7];
    const float* w1     = (const float*)d_in[8];
    const float* b1     = (const float*)d_in[9];
    const float* w2     = (const float*)d_in[10];
    const float* b2     = (const float*)d_in[11];
    const float* g1w    = (const float*)d_in[12];
    const float* bn1    = (const float*)d_in[13];
    const float* g2w    = (const float*)d_in[14];
    const float* bn2    = (const float*)d_in[15];

    float* out = (float*)d_out;
    float* p_out = out + OUT_ELEMS;

    void* sp = nullptr;
    cudaGetSymbolAddress(&sp, g_scratch);
    float* scr = (float*)sp;
    float* gx  = scr + OFF_X;
    float* gq  = scr + OFF_Q;
    float* gk  = scr + OFF_K;
    float* gvt = scr + OFF_VT;
    float* gao = scr + OFF_AO;
    float* gt1 = scr + OFF_T1;
    float* gh  = scr + OFF_H;
    float* gff = gq;  // reuse Q buffer for FFN intermediate (Q dead by then)

    // 1. x = transpose(src)
    transpose_src<<<S_LEN * B_SZ, 128>>>(src, gx);

    // 2. QKV projections (Q,K head-scatter; V transposed scatter)
    dim3 g512(D_MODEL / 128, M_ROWS / 128, 1);  // (4, 32)
    gemm_mma<0, 128><<<g512, 256>>>(gx, D_MODEL, 0, w_qs, D_MODEL, 0,
                                    D_MODEL, gq, nullptr, nullptr, 0);
    gemm_mma<0, 128><<<g512, 256>>>(gx, D_MODEL, 0, w_ks, D_MODEL, 0,
                                    D_MODEL, gk, nullptr, nullptr, 0);
    gemm_mma<1, 128><<<g512, 256>>>(gx, D_MODEL, 0, w_vs, D_MODEL, 0,
                                    D_MODEL, gvt, nullptr, nullptr, 0);

    // 3. scores = (Q K^T) * 0.125 * sph  -> staged in p_out
    dim3 gsc(S_LEN / 128, S_LEN / 128, B_SZ * H_HEADS);  // (16, 16, 16)
    gemm_mma<2, 128><<<gsc, 256>>>(
        gq, DK, (long long)S_LEN * DK, gk, DK, (long long)S_LEN * DK,
        DK, p_out, sph, nullptr, 0);

    // 4. softmax rows in place
    softmax_rows<<<B_SZ * H_HEADS * S_LEN, 256>>>(p_out);

    // 5. O = P @ V  (V^T is K-major) -> gao in (b,s,d) model layout
    dim3 gpv(1, S_LEN / 128, B_SZ * H_HEADS);            // (1, 16, 16)
    gemm_mma<3, 64><<<gpv, 256>>>(
        p_out, S_LEN, (long long)S_LEN * S_LEN, gvt, S_LEN,
        (long long)DK * S_LEN, S_LEN, gao, nullptr, nullptr, 0);

    // 6. fc projection + residual(x)
    gemm_mma<4, 128><<<g512, 256>>>(gao, D_MODEL, 0, w_fc, D_MODEL, 0,
                                    D_MODEL, gt1, gx, nullptr, D_MODEL);

    // 7. double LayerNorm
    ln_double_kernel<<<M_ROWS, 256>>>(gt1, gx, g_attn, b_attn, g1w, bn1, gh);

    // 8. FFN up: relu(h @ w1^T + b1)
    dim3 gffn(F_FFN / 128, M_ROWS / 128, 1);             // (16, 32)
    gemm_mma<5, 128><<<gffn, 256>>>(gh, D_MODEL, 0, w1, D_MODEL, 0,
                                    D_MODEL, gff, b1, nullptr, F_FFN);

    // 9. FFN down + b2 + residual(h)
    gemm_mma<6, 128><<<g512, 256>>>(gff, F_FFN, 0, w2, F_FFN, 0,
                                    F_FFN, gt1, b2, gh, D_MODEL);

    // 10. final LN + transposed store
    ln_final_kernel<<<M_ROWS, 256>>>(gt1, g2w, bn2, out);
}

// round 4
// speedup vs baseline: 6.2864x; 1.4863x over previous
#include <cuda_runtime.h>
#include <cstdint>
#include <cstddef>

// ---------------------------------------------------------------------------
// Problem constants
// ---------------------------------------------------------------------------
#define S_LEN 2048
#define B_SZ  2
#define D_MODEL 512
#define H_HEADS 8
#define DK 64
#define F_FFN 2048
#define M_ROWS (B_SZ * S_LEN)              // 4096
#define OUT_ELEMS (S_LEN * B_SZ * D_MODEL) // 2097152

// Scratch layout (floats)
#define OFF_X   0
#define OFF_Q   (1 * 2097152)
#define OFF_K   (2 * 2097152)
#define OFF_VT  (3 * 2097152)
#define OFF_AO  (4 * 2097152)
#define OFF_T1  (5 * 2097152)
#define OFF_H   (6 * 2097152)
#define SCRATCH_FLOATS (6 * 2097152 + 8388608)

__device__ float g_scratch[SCRATCH_FLOATS];

// ---------------------------------------------------------------------------
// PTX helpers
// ---------------------------------------------------------------------------
__device__ __forceinline__ uint32_t smem_to_u32(const void* p) {
    uint32_t a;
    asm("{ .reg .u64 t; cvta.to.shared.u64 t, %1; cvt.u32.u64 %0, t; }"
        : "=r"(a) : "l"(p));
    return a;
}

#define CP_ASYNC16(dst, src) \
    asm volatile("cp.async.cg.shared.global [%0], [%1], 16;\n" \
                 :: "r"(dst), "l"(src))
#define CP_COMMIT() asm volatile("cp.async.commit_group;\n" ::: "memory")
#define CP_WAIT1()  asm volatile("cp.async.wait_group 1;\n" ::: "memory")
#define CP_WAIT0()  asm volatile("cp.async.wait_group 0;\n" ::: "memory")

// m16n8k8 tf32 mma: d += A(16x8 row) * B(8x8 col)
__device__ __forceinline__ void mma_tf32(float (&dd)[4], const uint32_t (&a)[4],
                                         const uint32_t (&b)[2]) {
    asm volatile(
        "mma.sync.aligned.m16n8k8.row.col.f32.tf32.tf32.f32 "
        "{%0,%1,%2,%3}, {%4,%5,%6,%7}, {%8,%9}, {%0,%1,%2,%3};\n"
        : "+f"(dd[0]), "+f"(dd[1]), "+f"(dd[2]), "+f"(dd[3])
        : "r"(a[0]), "r"(a[1]), "r"(a[2]), "r"(a[3]), "r"(b[0]), "r"(b[1]));
}

// ---------------------------------------------------------------------------
// Transpose (S,B,D) -> (B,S,D)
// ---------------------------------------------------------------------------
__global__ void __launch_bounds__(128) transpose_src(const float* __restrict__ src,
                                                     float* __restrict__ x) {
    int id = blockIdx.x;
    int s = id >> 1;
    int b = id & 1;
    const float4* in = (const float4*)(src + (size_t)id * D_MODEL);
    float4* out = (float4*)(x + ((size_t)(b * S_LEN + s)) * D_MODEL);
    out[threadIdx.x] = in[threadIdx.x];
}

// ---------------------------------------------------------------------------
// tf32 mma.sync GEMM v2: BM=128, BN template, BK=32, 3-stage cp.async ring,
// 256 threads (8 warps: 4m x 2n), XOR-swizzled smem (8-chunk rows).
//
// EPI: 0 = fused QKV (z selects weight; z<2 plain store, z=2 V^T scatter)
//      2 = scores (*0.125*sph, per-head A/B offset)
//      3 = PV store to model layout
//      4 = +resid   5 = +bias,relu   6 = +bias +resid
// ---------------------------------------------------------------------------
#define STAGES 3

template <int EPI, int BN>
__global__ void __launch_bounds__(256, 2) gemm_mma(
    const float* __restrict__ A, int lda, long long aZ,
    const float* __restrict__ Bw, int ldb, long long bZ,
    int K, float* __restrict__ C,
    const float* __restrict__ aux1, const float* __restrict__ aux2, int ldc) {
    constexpr int NT = BN / 16;          // B 8-col tiles per warp
    extern __shared__ float dsm[];
    float* smA = dsm;                    // STAGES * 128 * 32
    float* smB = dsm + STAGES * 128 * 32;

    const int tid = threadIdx.x;
    const int w = tid >> 5, lane = tid & 31;
    const int g = lane >> 2, t = lane & 3;
    const int mw = w >> 1, nw = w & 1;
    const int m0 = blockIdx.y * 128, n0 = blockIdx.x * BN;
    const int z = blockIdx.z;

    const float* Bp;
    if (EPI == 0) {
        Bp = (z == 0) ? Bw : (z == 1) ? aux1 : aux2;
    } else if (EPI == 2) {
        size_t off = (size_t)(z >> 3) * (S_LEN * D_MODEL) + (size_t)(z & 7) * DK;
        A += off;
        Bp = Bw + off;
    } else {
        A += (size_t)z * aZ;
        Bp = Bw + (size_t)z * bZ;
    }

    const uint32_t sA = smem_to_u32(smA);
    const uint32_t sB = smem_to_u32(smB);

    float d[2][NT][4];
#pragma unroll
    for (int i = 0; i < 2; i++)
#pragma unroll
        for (int j = 0; j < NT; j++)
#pragma unroll
            for (int r = 0; r < 4; r++) d[i][j][r] = 0.f;

    const int NC = K >> 5;

    auto issue = [&](int kc, int stg) {
        int k0 = kc << 5;
#pragma unroll
        for (int i = 0; i < 4; i++) {
            int id = tid + (i << 8);          // 0..1023
            int r = id >> 3, q = id & 7;
            uint32_t dst = sA + ((stg * 4096 + r * 32 + ((q ^ (r & 7)) << 2)) << 2);
            CP_ASYNC16(dst, A + (size_t)(m0 + r) * lda + k0 + (q << 2));
        }
#pragma unroll
        for (int i = 0; i < BN / 32; i++) {
            int id = tid + (i << 8);
            int r = id >> 3, q = id & 7;
            uint32_t dst = sB + ((stg * (BN * 32) + r * 32 + ((q ^ (r & 7)) << 2)) << 2);
            CP_ASYNC16(dst, Bp + (size_t)(n0 + r) * ldb + k0 + (q << 2));
        }
        CP_COMMIT();
    };

    // prologue: up to STAGES-1 stages in flight
    issue(0, 0);
    if (NC > 1) issue(1, 1);

    for (int kc = 0; kc < NC; kc++) {
        if (kc == NC - 1) { CP_WAIT0(); } else { CP_WAIT1(); }
        __syncthreads();
        if (kc + 2 < NC) issue(kc + 2, (kc + 2) % STAGES);

        int buf = kc % STAGES;
        const float* Ab = smA + buf * 4096;
        const float* Bb = smB + buf * (BN * 32);
#pragma unroll
        for (int ks = 0; ks < 4; ks++) {
            // physical column chunks: (2ks ^ row&7), row&7 == g for all our rows
            const int pc0 = (((2 * ks) ^ g) << 2) + t;
            const int pc1 = (((2 * ks + 1) ^ g) << 2) + t;
            uint32_t a[2][4];
#pragma unroll
            for (int mtw = 0; mtw < 2; mtw++) {
                int row = (mw * 2 + mtw) * 16 + g;
                a[mtw][0] = __float_as_uint(Ab[row * 32 + pc0]);
                a[mtw][1] = __float_as_uint(Ab[(row + 8) * 32 + pc0]);
                a[mtw][2] = __float_as_uint(Ab[row * 32 + pc1]);
                a[mtw][3] = __float_as_uint(Ab[(row + 8) * 32 + pc1]);
            }
            uint32_t b[NT][2];
#pragma unroll
            for (int ntw = 0; ntw < NT; ntw++) {
                int nr = (nw * NT + ntw) * 8 + g;
                b[ntw][0] = __float_as_uint(Bb[nr * 32 + pc0]);
                b[ntw][1] = __float_as_uint(Bb[nr * 32 + pc1]);
            }
#pragma unroll
            for (int mtw = 0; mtw < 2; mtw++)
#pragma unroll
                for (int ntw = 0; ntw < NT; ntw++)
                    mma_tf32(d[mtw][ntw], a[mtw], b[ntw]);
        }
        __syncthreads();
    }

    // ---------------- epilogue ----------------
#pragma unroll
    for (int mtw = 0; mtw < 2; mtw++)
#pragma unroll
        for (int ntw = 0; ntw < NT; ntw++)
#pragma unroll
            for (int half = 0; half < 2; half++) {
                int m = m0 + mw * 32 + mtw * 16 + half * 8 + g;
                int n = n0 + nw * (BN / 2) + ntw * 8 + t * 2;
                float v0 = d[mtw][ntw][half * 2 + 0];
                float v1 = d[mtw][ntw][half * 2 + 1];
                if (EPI == 0) {
                    if (z < 2) {          // Q/K plain (m, 512)
                        float* dst = C + (size_t)z * 2097152 +
                                     (size_t)m * D_MODEL + n;
                        *(float2*)dst = make_float2(v0, v1);
                    } else {              // V^T scatter to (b,h,dk,s)
                        int b = m >> 11, s = m & (S_LEN - 1);
                        int h = n >> 6, dd = n & 63;
                        float* C2 = C + 2 * 2097152;
                        size_t base = ((size_t)((b << 3) + h) * DK + dd) * S_LEN + s;
                        C2[base] = v0;
                        C2[base + S_LEN] = v1;
                    }
                } else if (EPI == 2) {    // scores: * 0.125 * sph
                    size_t idx = ((size_t)z * S_LEN + m) * S_LEN + n;
                    float2 sp = *(const float2*)(aux1 + idx);
                    *(float2*)(C + idx) = make_float2(v0 * 0.125f * sp.x,
                                                      v1 * 0.125f * sp.y);
                } else if (EPI == 3) {    // PV output -> (b, s, h*64+n)
                    size_t dst = ((size_t)((z >> 3) * S_LEN + m)) * D_MODEL +
                                 (z & 7) * DK + n;
                    *(float2*)(C + dst) = make_float2(v0, v1);
                } else if (EPI == 4) {    // + resid
                    size_t o = (size_t)m * ldc + n;
                    float2 rr = *(const float2*)(aux1 + o);
                    *(float2*)(C + o) = make_float2(v0 + rr.x, v1 + rr.y);
                } else if (EPI == 5) {    // + bias, relu
                    size_t o = (size_t)m * ldc + n;
                    float2 bb = *(const float2*)(aux1 + n);
                    *(float2*)(C + o) = make_float2(fmaxf(v0 + bb.x, 0.f),
                                                    fmaxf(v1 + bb.y, 0.f));
                } else {                  // + bias + resid
                    size_t o = (size_t)m * ldc + n;
                    float2 bb = *(const float2*)(aux1 + n);
                    float2 rr = *(const float2*)(aux2 + o);
                    *(float2*)(C + o) = make_float2(v0 + bb.x + rr.x,
                                                    v1 + bb.y + rr.y);
                }
            }
}

// ---------------------------------------------------------------------------
// Row softmax in place over p (32768 rows x 2048)
// ---------------------------------------------------------------------------
__global__ void __launch_bounds__(256) softmax_rows(float* __restrict__ p) {
    __shared__ float red[8];
    int t = threadIdx.x;
    float4* row = (float4*)(p + (size_t)blockIdx.x * S_LEN);
    float4 a = row[t], b = row[t + 256];
    float mx = fmaxf(fmaxf(fmaxf(a.x, a.y), fmaxf(a.z, a.w)),
                     fmaxf(fmaxf(b.x, b.y), fmaxf(b.z, b.w)));
#pragma unroll
    for (int o = 16; o; o >>= 1) mx = fmaxf(mx, __shfl_xor_sync(0xffffffffu, mx, o));
    if ((t & 31) == 0) red[t >> 5] = mx;
    __syncthreads();
    float gmx = red[0];
#pragma unroll
    for (int i = 1; i < 8; i++) gmx = fmaxf(gmx, red[i]);
    __syncthreads();
    a.x = __expf(a.x - gmx); a.y = __expf(a.y - gmx);
    a.z = __expf(a.z - gmx); a.w = __expf(a.w - gmx);
    b.x = __expf(b.x - gmx); b.y = __expf(b.y - gmx);
    b.z = __expf(b.z - gmx); b.w = __expf(b.w - gmx);
    float ls = a.x + a.y + a.z + a.w + b.x + b.y + b.z + b.w;
#pragma unroll
    for (int o = 16; o; o >>= 1) ls += __shfl_xor_sync(0xffffffffu, ls, o);
    if ((t & 31) == 0) red[t >> 5] = ls;
    __syncthreads();
    float tot = red[0];
#pragma unroll
    for (int i = 1; i < 8; i++) tot += red[i];
    float inv = 1.0f / tot;
    a.x *= inv; a.y *= inv; a.z *= inv; a.w *= inv;
    b.x *= inv; b.y *= inv; b.z *= inv; b.w *= inv;
    row[t] = a;
    row[t + 256] = b;
}

// ---------------------------------------------------------------------------
// LayerNorm kernels
// ---------------------------------------------------------------------------
__device__ __forceinline__ float blockSum256(float v, float* sred) {
#pragma unroll
    for (int o = 16; o; o >>= 1) v += __shfl_xor_sync(0xffffffffu, v, o);
    __syncthreads();
    if ((threadIdx.x & 31) == 0) sred[threadIdx.x >> 5] = v;
    __syncthreads();
    float s = sred[0];
#pragma unroll
    for (int i = 1; i < 8; i++) s += sred[i];
    return s;
}

__global__ void __launch_bounds__(256) ln_double_kernel(
    const float* __restrict__ tin, const float* __restrict__ xin,
    const float* __restrict__ ga, const float* __restrict__ ba,
    const float* __restrict__ g1w, const float* __restrict__ b1w,
    float* __restrict__ hout) {
    __shared__ float sred[8];
    int m = blockIdx.x, t = threadIdx.x;
    float2 v = ((const float2*)(tin + (size_t)m * D_MODEL))[t];
    float2 xv = ((const float2*)(xin + (size_t)m * D_MODEL))[t];
    float mu = blockSum256(v.x + v.y, sred) * (1.f / 512.f);
    float dx = v.x - mu, dy = v.y - mu;
    float var = blockSum256(dx * dx + dy * dy, sred) * (1.f / 512.f);
    float rs = rsqrtf(var + 1e-6f);
    int d0 = t * 2;
    float u0 = xv.x + dx * rs * ga[d0] + ba[d0];
    float u1 = xv.y + dy * rs * ga[d0 + 1] + ba[d0 + 1];
    mu = blockSum256(u0 + u1, sred) * (1.f / 512.f);
    dx = u0 - mu; dy = u1 - mu;
    var = blockSum256(dx * dx + dy * dy, sred) * (1.f / 512.f);
    rs = rsqrtf(var + 1e-5f);
    float2 hv = make_float2(dx * rs * g1w[d0] + b1w[d0],
                            dy * rs * g1w[d0 + 1] + b1w[d0 + 1]);
    ((float2*)(hout + (size_t)m * D_MODEL))[t] = hv;
}

__global__ void __launch_bounds__(256) ln_final_kernel(
    const float* __restrict__ tin, const float* __restrict__ g2w,
    const float* __restrict__ b2w, float* __restrict__ out) {
    __shared__ float sred[8];
    int m = blockIdx.x, t = threadIdx.x;
    float2 v = ((const float2*)(tin + (size_t)m * D_MODEL))[t];
    float mu = blockSum256(v.x + v.y, sred) * (1.f / 512.f);
    float dx = v.x - mu, dy = v.y - mu;
    float var = blockSum256(dx * dx + dy * dy, sred) * (1.f / 512.f);
    float rs = rsqrtf(var + 1e-5f);
    int d0 = t * 2;
    int b = m >> 11;
    int s = m & (S_LEN - 1);
    float2 ov = make_float2(dx * rs * g2w[d0] + b2w[d0],
                            dy * rs * g2w[d0 + 1] + b2w[d0 + 1]);
    ((float2*)(out + ((size_t)(s * B_SZ + b)) * D_MODEL))[t] = ov;
}

// ---------------------------------------------------------------------------
// Launch
// ---------------------------------------------------------------------------
#define SMEM_BN128 (STAGES * (128 + 128) * 32 * 4)   // 98304
#define SMEM_BN64  (STAGES * (128 + 64) * 32 * 4)    // 73728

extern "C" void kernel_launch(void* const* d_in, const int* in_sizes, int n_in,
                              void* d_out, int out_size) {
    const float* src    = (const float*)d_in[0];
    const float* sph    = (const float*)d_in[1];
    const float* w_qs   = (const float*)d_in[2];
    const float* w_ks   = (const float*)d_in[3];
    const float* w_vs   = (const float*)d_in[4];
    const float* w_fc   = (const float*)d_in[5];
    const float* g_attn = (const float*)d_in[6];
    const float* b_attn = (const float*)d_in[7];
    const float* w1     = (const float*)d_in[8];
    const float* b1     = (const float*)d_in[9];
    const float* w2     = (const float*)d_in[10];
    const float* b2     = (const float*)d_in[11];
    const float* g1w    = (const float*)d_in[12];
    const float* bn1    = (const float*)d_in[13];
    const float* g2w    = (const float*)d_in[14];
    const float* bn2    = (const float*)d_in[15];

    float* out = (float*)d_out;
    float* p_out = out + OUT_ELEMS;

    void* sp = nullptr;
    cudaGetSymbolAddress(&sp, g_scratch);
    float* scr = (float*)sp;
    float* gx  = scr + OFF_X;
    float* gq  = scr + OFF_Q;
    float* gk  = scr + OFF_K;
    float* gvt = scr + OFF_VT;
    float* gao = scr + OFF_AO;
    float* gt1 = scr + OFF_T1;
    float* gh  = scr + OFF_H;
    float* gff = gq;  // FFN intermediate reuses Q..AO region (dead by then)

    static bool attr_done = false;
    if (!attr_done) {
        cudaFuncSetAttribute(gemm_mma<0, 128>, cudaFuncAttributeMaxDynamicSharedMemorySize, SMEM_BN128);
        cudaFuncSetAttribute(gemm_mma<2, 128>, cudaFuncAttributeMaxDynamicSharedMemorySize, SMEM_BN128);
        cudaFuncSetAttribute(gemm_mma<3, 64>,  cudaFuncAttributeMaxDynamicSharedMemorySize, SMEM_BN64);
        cudaFuncSetAttribute(gemm_mma<4, 64>,  cudaFuncAttributeMaxDynamicSharedMemorySize, SMEM_BN64);
        cudaFuncSetAttribute(gemm_mma<5, 128>, cudaFuncAttributeMaxDynamicSharedMemorySize, SMEM_BN128);
        cudaFuncSetAttribute(gemm_mma<6, 64>,  cudaFuncAttributeMaxDynamicSharedMemorySize, SMEM_BN64);
        attr_done = true;
    }

    // 1. x = transpose(src)
    transpose_src<<<S_LEN * B_SZ, 128>>>(src, gx);

    // 2. fused QKV projections: z=0 Q plain, z=1 K plain, z=2 V^T scatter
    dim3 gqkv(D_MODEL / 128, M_ROWS / 128, 3);   // (4, 32, 3) = 384 CTAs
    gemm_mma<0, 128><<<gqkv, 256, SMEM_BN128>>>(gx, D_MODEL, 0, w_qs, D_MODEL, 0,
                                                D_MODEL, gq, w_ks, w_vs, 0);

    // 3. scores = (Q K^T) * 0.125 * sph  -> staged in p_out
    dim3 gsc(S_LEN / 128, S_LEN / 128, B_SZ * H_HEADS);  // (16, 16, 16)
    gemm_mma<2, 128><<<gsc, 256, SMEM_BN128>>>(
        gq, D_MODEL, 0, gk, D_MODEL, 0, DK, p_out, sph, nullptr, 0);

    // 4. softmax rows in place
    softmax_rows<<<B_SZ * H_HEADS * S_LEN, 256>>>(p_out);

    // 5. O = P @ V  (V^T K-major) -> gao in (b,s,d) model layout
    dim3 gpv(1, S_LEN / 128, B_SZ * H_HEADS);            // (1, 16, 16)
    gemm_mma<3, 64><<<gpv, 256, SMEM_BN64>>>(
        p_out, S_LEN, (long long)S_LEN * S_LEN, gvt, S_LEN,
        (long long)DK * S_LEN, S_LEN, gao, nullptr, nullptr, 0);

    // 6. fc projection + residual(x)
    dim3 gfc(D_MODEL / 64, M_ROWS / 128, 1);             // (8, 32)
    gemm_mma<4, 64><<<gfc, 256, SMEM_BN64>>>(gao, D_MODEL, 0, w_fc, D_MODEL, 0,
                                             D_MODEL, gt1, gx, nullptr, D_MODEL);

    // 7. double LayerNorm
    ln_double_kernel<<<M_ROWS, 256>>>(gt1, gx, g_attn, b_attn, g1w, bn1, gh);

    // 8. FFN up: relu(h @ w1^T + b1)
    dim3 gffn(F_FFN / 128, M_ROWS / 128, 1);             // (16, 32)
    gemm_mma<5, 128><<<gffn, 256, SMEM_BN128>>>(gh, D_MODEL, 0, w1, D_MODEL, 0,
                                                D_MODEL, gff, b1, nullptr, F_FFN);

    // 9. FFN down + b2 + residual(h)
    gemm_mma<6, 64><<<gfc, 256, SMEM_BN64>>>(gff, F_FFN, 0, w2, F_FFN, 0,
                                             F_FFN, gt1, b2, gh, D_MODEL);

    // 10. final LN + transposed store
    ln_final_kernel<<<M_ROWS, 256>>>(gt1, g2w, bn2, out);
}

// round 5
// speedup vs baseline: 6.4885x; 1.0322x over previous
#include <cuda_runtime.h>
#include <cuda_fp16.h>
#include <cstdint>
#include <cstddef>

// ---------------------------------------------------------------------------
// Problem constants
// ---------------------------------------------------------------------------
#define S_LEN 2048
#define B_SZ  2
#define D_MODEL 512
#define H_HEADS 8
#define DK 64
#define F_FFN 2048
#define M_ROWS (B_SZ * S_LEN)              // 4096
#define OUT_ELEMS (S_LEN * B_SZ * D_MODEL) // 2097152

// Scratch layout (float offsets)
#define OFF_Q   0
#define OFF_K   2097152
#define OFF_AO  4194304
#define OFF_T1  6291456
#define OFF_H   8388608
#define OFF_FF  10485760              // 8388608 floats
#define OFF_VTH 18874368              // fp16 V^T: 2097152 halves (1M floats)
#define OFF_SH  19922944              // fp16 scores: 67108864 halves
#define OFF_PH  53477376              // fp16 p
#define SCRATCH_FLOATS 87031808

__device__ float g_scratch[SCRATCH_FLOATS];

// ---------------------------------------------------------------------------
// PTX helpers
// ---------------------------------------------------------------------------
__device__ __forceinline__ uint32_t smem_to_u32(const void* p) {
    uint32_t a;
    asm("{ .reg .u64 t; cvta.to.shared.u64 t, %1; cvt.u32.u64 %0, t; }"
        : "=r"(a) : "l"(p));
    return a;
}

#define CP_ASYNC16(dst, src) \
    asm volatile("cp.async.cg.shared.global [%0], [%1], 16;\n" \
                 :: "r"(dst), "l"(src))
#define CP_COMMIT() asm volatile("cp.async.commit_group;\n" ::: "memory")
#define CP_WAIT1()  asm volatile("cp.async.wait_group 1;\n" ::: "memory")
#define CP_WAIT0()  asm volatile("cp.async.wait_group 0;\n" ::: "memory")

__device__ __forceinline__ void mma_tf32(float (&dd)[4], const uint32_t (&a)[4],
                                         const uint32_t (&b)[2]) {
    asm volatile(
        "mma.sync.aligned.m16n8k8.row.col.f32.tf32.tf32.f32 "
        "{%0,%1,%2,%3}, {%4,%5,%6,%7}, {%8,%9}, {%0,%1,%2,%3};\n"
        : "+f"(dd[0]), "+f"(dd[1]), "+f"(dd[2]), "+f"(dd[3])
        : "r"(a[0]), "r"(a[1]), "r"(a[2]), "r"(a[3]), "r"(b[0]), "r"(b[1]));
}

__device__ __forceinline__ void mma_f16(float (&dd)[4], const uint32_t (&a)[4],
                                        const uint32_t (&b)[2]) {
    asm volatile(
        "mma.sync.aligned.m16n8k16.row.col.f32.f16.f16.f32 "
        "{%0,%1,%2,%3}, {%4,%5,%6,%7}, {%8,%9}, {%0,%1,%2,%3};\n"
        : "+f"(dd[0]), "+f"(dd[1]), "+f"(dd[2]), "+f"(dd[3])
        : "r"(a[0]), "r"(a[1]), "r"(a[2]), "r"(a[3]), "r"(b[0]), "r"(b[1]));
}

// permuted src row: x[m] = src[(s*B + b)] with m = b*S + s
__device__ __forceinline__ int perm_row(int m) {
    return ((m & (S_LEN - 1)) << 1) + (m >> 11);
}

// ---------------------------------------------------------------------------
// tf32 mma.sync GEMM: BM=128, BN template, BK=32, 3-stage cp.async ring,
// 256 threads (8 warps: 4m x 2n), XOR-swizzled smem.
//
// EPI: 0 = fused QKV (APERM; z=0 Q, z=1 K plain fp32; z=2 V^T fp16 scatter)
//      2 = scores -> fp16 (*0.125*sph), per-head A/B offset
//      4 = +resid (resid = src, perm-read)
//      5 = +bias,relu   6 = +bias +resid
// ---------------------------------------------------------------------------
#define STAGES 3

template <int EPI, int BN, bool APERM>
__global__ void __launch_bounds__(256, 2) gemm_mma(
    const float* __restrict__ A, int lda, long long aZ,
    const float* __restrict__ Bw, int ldb, long long bZ,
    int K, float* __restrict__ C,
    const float* __restrict__ aux1, const float* __restrict__ aux2, int ldc,
    __half* __restrict__ Chalf) {
    constexpr int NT = BN / 16;
    extern __shared__ float dsm[];
    float* smA = dsm;
    float* smB = dsm + STAGES * 128 * 32;

    const int tid = threadIdx.x;
    const int w = tid >> 5, lane = tid & 31;
    const int g = lane >> 2, t = lane & 3;
    const int mw = w >> 1, nw = w & 1;
    const int m0 = blockIdx.y * 128, n0 = blockIdx.x * BN;
    const int z = blockIdx.z;

    const float* Bp;
    if (EPI == 0) {
        Bp = (z == 0) ? Bw : (z == 1) ? aux1 : aux2;
    } else if (EPI == 2) {
        size_t off = (size_t)(z >> 3) * (S_LEN * D_MODEL) + (size_t)(z & 7) * DK;
        A += off;
        Bp = Bw + off;
    } else {
        A += (size_t)z * aZ;
        Bp = Bw + (size_t)z * bZ;
    }

    const uint32_t sA = smem_to_u32(smA);
    const uint32_t sB = smem_to_u32(smB);

    float d[2][NT][4];
#pragma unroll
    for (int i = 0; i < 2; i++)
#pragma unroll
        for (int j = 0; j < NT; j++)
#pragma unroll
            for (int r = 0; r < 4; r++) d[i][j][r] = 0.f;

    const int NC = K >> 5;

    auto issue = [&](int kc, int stg) {
        int k0 = kc << 5;
#pragma unroll
        for (int i = 0; i < 4; i++) {
            int id = tid + (i << 8);
            int r = id >> 3, q = id & 7;
            uint32_t dst = sA + ((stg * 4096 + r * 32 + ((q ^ (r & 7)) << 2)) << 2);
            int gr = m0 + r;
            const float* src = A + (size_t)(APERM ? perm_row(gr) : gr) * lda +
                               k0 + (q << 2);
            CP_ASYNC16(dst, src);
        }
#pragma unroll
        for (int i = 0; i < BN / 32; i++) {
            int id = tid + (i << 8);
            int r = id >> 3, q = id & 7;
            uint32_t dst = sB + ((stg * (BN * 32) + r * 32 + ((q ^ (r & 7)) << 2)) << 2);
            CP_ASYNC16(dst, Bp + (size_t)(n0 + r) * ldb + k0 + (q << 2));
        }
        CP_COMMIT();
    };

    issue(0, 0);
    if (NC > 1) issue(1, 1);

    for (int kc = 0; kc < NC; kc++) {
        if (kc == NC - 1) { CP_WAIT0(); } else { CP_WAIT1(); }
        __syncthreads();
        if (kc + 2 < NC) issue(kc + 2, (kc + 2) % STAGES);

        int buf = kc % STAGES;
        const float* Ab = smA + buf * 4096;
        const float* Bb = smB + buf * (BN * 32);
#pragma unroll
        for (int ks = 0; ks < 4; ks++) {
            const int pc0 = (((2 * ks) ^ g) << 2) + t;
            const int pc1 = (((2 * ks + 1) ^ g) << 2) + t;
            uint32_t a[2][4];
#pragma unroll
            for (int mtw = 0; mtw < 2; mtw++) {
                int row = (mw * 2 + mtw) * 16 + g;
                a[mtw][0] = __float_as_uint(Ab[row * 32 + pc0]);
                a[mtw][1] = __float_as_uint(Ab[(row + 8) * 32 + pc0]);
                a[mtw][2] = __float_as_uint(Ab[row * 32 + pc1]);
                a[mtw][3] = __float_as_uint(Ab[(row + 8) * 32 + pc1]);
            }
            uint32_t b[NT][2];
#pragma unroll
            for (int ntw = 0; ntw < NT; ntw++) {
                int nr = (nw * NT + ntw) * 8 + g;
                b[ntw][0] = __float_as_uint(Bb[nr * 32 + pc0]);
                b[ntw][1] = __float_as_uint(Bb[nr * 32 + pc1]);
            }
#pragma unroll
            for (int mtw = 0; mtw < 2; mtw++)
#pragma unroll
                for (int ntw = 0; ntw < NT; ntw++)
                    mma_tf32(d[mtw][ntw], a[mtw], b[ntw]);
        }
        __syncthreads();
    }

    // ---------------- epilogue ----------------
#pragma unroll
    for (int mtw = 0; mtw < 2; mtw++)
#pragma unroll
        for (int ntw = 0; ntw < NT; ntw++)
#pragma unroll
            for (int half = 0; half < 2; half++) {
                int m = m0 + mw * 32 + mtw * 16 + half * 8 + g;
                int n = n0 + nw * (BN / 2) + ntw * 8 + t * 2;
                float v0 = d[mtw][ntw][half * 2 + 0];
                float v1 = d[mtw][ntw][half * 2 + 1];
                if (EPI == 0) {
                    if (z < 2) {          // Q/K plain (m, 512)
                        float* dst = C + (size_t)z * 2097152 +
                                     (size_t)m * D_MODEL + n;
                        *(float2*)dst = make_float2(v0, v1);
                    } else {              // V^T fp16 scatter to (b,h,dk,s)
                        int b = m >> 11, s = m & (S_LEN - 1);
                        int h = n >> 6, dd = n & 63;
                        size_t base = ((size_t)((b << 3) + h) * DK + dd) * S_LEN + s;
                        Chalf[base] = __float2half(v0);
                        Chalf[base + S_LEN] = __float2half(v1);
                    }
                } else if (EPI == 2) {    // scores fp16: * 0.125 * sph
                    size_t idx = ((size_t)z * S_LEN + m) * S_LEN + n;
                    float2 sp = *(const float2*)(aux1 + idx);
                    *(__half2*)(Chalf + idx) =
                        __floats2half2_rn(v0 * 0.125f * sp.x, v1 * 0.125f * sp.y);
                } else if (EPI == 4) {    // + resid (src, perm)
                    size_t o = (size_t)m * ldc + n;
                    const float* rsrc = aux1 + (size_t)perm_row(m) * D_MODEL + n;
                    float2 rr = *(const float2*)rsrc;
                    *(float2*)(C + o) = make_float2(v0 + rr.x, v1 + rr.y);
                } else if (EPI == 5) {    // + bias, relu
                    size_t o = (size_t)m * ldc + n;
                    float2 bb = *(const float2*)(aux1 + n);
                    *(float2*)(C + o) = make_float2(fmaxf(v0 + bb.x, 0.f),
                                                    fmaxf(v1 + bb.y, 0.f));
                } else {                  // + bias + resid
                    size_t o = (size_t)m * ldc + n;
                    float2 bb = *(const float2*)(aux1 + n);
                    float2 rr = *(const float2*)(aux2 + o);
                    *(float2*)(C + o) = make_float2(v0 + bb.x + rr.x,
                                                    v1 + bb.y + rr.y);
                }
            }
}

// ---------------------------------------------------------------------------
// PV GEMM (fp16 x fp16 -> fp32): O[bh](m, dk) = sum_k P[bh](m,k) * Vt[bh](dk,k)
// BM=128, BN=64 (=DK), BK=32 halves, 3-stage cp.async, m16n8k16.
// Output scattered to gao model layout (b, s, h*64+dk).
// ---------------------------------------------------------------------------
__global__ void __launch_bounds__(256) pv_f16(
    const __half* __restrict__ ph, const __half* __restrict__ vth,
    float* __restrict__ C) {
    __shared__ __half smA[STAGES][128 * 32];
    __shared__ __half smB[STAGES][64 * 32];

    const int tid = threadIdx.x;
    const int w = tid >> 5, lane = tid & 31;
    const int g = lane >> 2, t = lane & 3;
    const int mw = w >> 1, nw = w & 1;
    const int m0 = blockIdx.x * 128;
    const int bh = blockIdx.y;

    const __half* Ap = ph + (size_t)bh * S_LEN * S_LEN;
    const __half* Bp = vth + (size_t)bh * DK * S_LEN;

    const uint32_t sA = smem_to_u32(smA);
    const uint32_t sB = smem_to_u32(smB);

    float d[2][4][4];
#pragma unroll
    for (int i = 0; i < 2; i++)
#pragma unroll
        for (int j = 0; j < 4; j++)
#pragma unroll
            for (int r = 0; r < 4; r++) d[i][j][r] = 0.f;

    const int NC = S_LEN / 32;   // 64

    auto issue = [&](int kc, int stg) {
        int k0 = kc << 5;
#pragma unroll
        for (int i = 0; i < 2; i++) {
            int id = tid + (i << 8);          // 0..511 : 128 rows x 4 chunks
            int r = id >> 2, c = id & 3;
            uint32_t dst = sA + stg * 8192 + r * 64 + ((c ^ (r & 3)) << 4);
            CP_ASYNC16(dst, Ap + (size_t)(m0 + r) * S_LEN + k0 + (c << 3));
        }
        {
            int r = tid >> 2, c = tid & 3;    // 64 rows x 4 chunks
            uint32_t dst = sB + stg * 4096 + r * 64 + ((c ^ (r & 3)) << 4);
            CP_ASYNC16(dst, Bp + (size_t)r * S_LEN + k0 + (c << 3));
        }
        CP_COMMIT();
    };

    issue(0, 0);
    issue(1, 1);

    for (int kc = 0; kc < NC; kc++) {
        if (kc == NC - 1) { CP_WAIT0(); } else { CP_WAIT1(); }
        __syncthreads();
        if (kc + 2 < NC) issue(kc + 2, (kc + 2) % STAGES);

        int buf = kc % STAGES;
        const __half* Ab = smA[buf];
        const __half* Bb = smB[buf];
#pragma unroll
        for (int ks = 0; ks < 2; ks++) {
            // half-index within row: lo chunk = 2ks, hi chunk = 2ks+1
            uint32_t a[2][4];
#pragma unroll
            for (int mtw = 0; mtw < 2; mtw++) {
                int r0 = (mw * 2 + mtw) * 16 + g;
                int r1 = r0 + 8;
                int lo0 = ((2 * ks) ^ (r0 & 3)) * 8 + 2 * t;
                int hi0 = ((2 * ks + 1) ^ (r0 & 3)) * 8 + 2 * t;
                int lo1 = ((2 * ks) ^ (r1 & 3)) * 8 + 2 * t;
                int hi1 = ((2 * ks + 1) ^ (r1 & 3)) * 8 + 2 * t;
                a[mtw][0] = *(const uint32_t*)(Ab + r0 * 32 + lo0);
                a[mtw][1] = *(const uint32_t*)(Ab + r1 * 32 + lo1);
                a[mtw][2] = *(const uint32_t*)(Ab + r0 * 32 + hi0);
                a[mtw][3] = *(const uint32_t*)(Ab + r1 * 32 + hi1);
            }
            uint32_t b[4][2];
#pragma unroll
            for (int ntw = 0; ntw < 4; ntw++) {
                int nr = nw * 32 + ntw * 8 + g;
                int lo = ((2 * ks) ^ (nr & 3)) * 8 + 2 * t;
                int hi = ((2 * ks + 1) ^ (nr & 3)) * 8 + 2 * t;
                b[ntw][0] = *(const uint32_t*)(Bb + nr * 32 + lo);
                b[ntw][1] = *(const uint32_t*)(Bb + nr * 32 + hi);
            }
#pragma unroll
            for (int mtw = 0; mtw < 2; mtw++)
#pragma unroll
                for (int ntw = 0; ntw < 4; ntw++)
                    mma_f16(d[mtw][ntw], a[mtw], b[ntw]);
        }
        __syncthreads();
    }

    int b = bh >> 3, h = bh & 7;
#pragma unroll
    for (int mtw = 0; mtw < 2; mtw++)
#pragma unroll
        for (int ntw = 0; ntw < 4; ntw++)
#pragma unroll
            for (int half = 0; half < 2; half++) {
                int m = m0 + mw * 32 + mtw * 16 + half * 8 + g;
                int n = nw * 32 + ntw * 8 + t * 2;
                float v0 = d[mtw][ntw][half * 2 + 0];
                float v1 = d[mtw][ntw][half * 2 + 1];
                size_t dst = ((size_t)(b * S_LEN + m)) * D_MODEL + h * DK + n;
                *(float2*)(C + dst) = make_float2(v0, v1);
            }
}

// ---------------------------------------------------------------------------
// Row softmax: read fp16 scores, write fp32 p (output) + fp16 p (for PV)
// ---------------------------------------------------------------------------
__global__ void __launch_bounds__(256) softmax_rows(
    const __half* __restrict__ sh, float* __restrict__ pout,
    __half* __restrict__ ph) {
    __shared__ float red[8];
    int t = threadIdx.x;
    size_t rowoff = (size_t)blockIdx.x * S_LEN;
    uint4 raw = ((const uint4*)(sh + rowoff))[t];
    const __half2* h2 = (const __half2*)&raw;
    float2 f[4];
#pragma unroll
    for (int i = 0; i < 4; i++) f[i] = __half22float2(h2[i]);

    float mx = -1e30f;
#pragma unroll
    for (int i = 0; i < 4; i++) mx = fmaxf(mx, fmaxf(f[i].x, f[i].y));
#pragma unroll
    for (int o = 16; o; o >>= 1) mx = fmaxf(mx, __shfl_xor_sync(0xffffffffu, mx, o));
    if ((t & 31) == 0) red[t >> 5] = mx;
    __syncthreads();
    float gmx = red[0];
#pragma unroll
    for (int i = 1; i < 8; i++) gmx = fmaxf(gmx, red[i]);
    __syncthreads();

    float sum = 0.f;
#pragma unroll
    for (int i = 0; i < 4; i++) {
        f[i].x = __expf(f[i].x - gmx);
        f[i].y = __expf(f[i].y - gmx);
        sum += f[i].x + f[i].y;
    }
#pragma unroll
    for (int o = 16; o; o >>= 1) sum += __shfl_xor_sync(0xffffffffu, sum, o);
    if ((t & 31) == 0) red[t >> 5] = sum;
    __syncthreads();
    float tot = red[0];
#pragma unroll
    for (int i = 1; i < 8; i++) tot += red[i];
    float inv = 1.0f / tot;

    float4* po = (float4*)(pout + rowoff) + t * 2;
    po[0] = make_float4(f[0].x * inv, f[0].y * inv, f[1].x * inv, f[1].y * inv);
    po[1] = make_float4(f[2].x * inv, f[2].y * inv, f[3].x * inv, f[3].y * inv);

    uint4 packed;
    __half2* ph2 = (__half2*)&packed;
#pragma unroll
    for (int i = 0; i < 4; i++)
        ph2[i] = __floats2half2_rn(f[i].x * inv, f[i].y * inv);
    ((uint4*)(ph + rowoff))[t] = packed;
}

// ---------------------------------------------------------------------------
// LayerNorm kernels
// ---------------------------------------------------------------------------
__device__ __forceinline__ float blockSum256(float v, float* sred) {
#pragma unroll
    for (int o = 16; o; o >>= 1) v += __shfl_xor_sync(0xffffffffu, v, o);
    __syncthreads();
    if ((threadIdx.x & 31) == 0) sred[threadIdx.x >> 5] = v;
    __syncthreads();
    float s = sred[0];
#pragma unroll
    for (int i = 1; i < 8; i++) s += sred[i];
    return s;
}

__global__ void __launch_bounds__(256) ln_double_kernel(
    const float* __restrict__ tin, const float* __restrict__ src,
    const float* __restrict__ ga, const float* __restrict__ ba,
    const float* __restrict__ g1w, const float* __restrict__ b1w,
    float* __restrict__ hout) {
    __shared__ float sred[8];
    int m = blockIdx.x, t = threadIdx.x;
    float2 v = ((const float2*)(tin + (size_t)m * D_MODEL))[t];
    float2 xv = ((const float2*)(src + (size_t)perm_row(m) * D_MODEL))[t];
    float mu = blockSum256(v.x + v.y, sred) * (1.f / 512.f);
    float dx = v.x - mu, dy = v.y - mu;
    float var = blockSum256(dx * dx + dy * dy, sred) * (1.f / 512.f);
    float rs = rsqrtf(var + 1e-6f);
    int d0 = t * 2;
    float u0 = xv.x + dx * rs * ga[d0] + ba[d0];
    float u1 = xv.y + dy * rs * ga[d0 + 1] + ba[d0 + 1];
    mu = blockSum256(u0 + u1, sred) * (1.f / 512.f);
    dx = u0 - mu; dy = u1 - mu;
    var = blockSum256(dx * dx + dy * dy, sred) * (1.f / 512.f);
    rs = rsqrtf(var + 1e-5f);
    float2 hv = make_float2(dx * rs * g1w[d0] + b1w[d0],
                            dy * rs * g1w[d0 + 1] + b1w[d0 + 1]);
    ((float2*)(hout + (size_t)m * D_MODEL))[t] = hv;
}

__global__ void __launch_bounds__(256) ln_final_kernel(
    const float* __restrict__ tin, const float* __restrict__ g2w,
    const float* __restrict__ b2w, float* __restrict__ out) {
    __shared__ float sred[8];
    int m = blockIdx.x, t = threadIdx.x;
    float2 v = ((const float2*)(tin + (size_t)m * D_MODEL))[t];
    float mu = blockSum256(v.x + v.y, sred) * (1.f / 512.f);
    float dx = v.x - mu, dy = v.y - mu;
    float var = blockSum256(dx * dx + dy * dy, sred) * (1.f / 512.f);
    float rs = rsqrtf(var + 1e-5f);
    int d0 = t * 2;
    int b = m >> 11;
    int s = m & (S_LEN - 1);
    float2 ov = make_float2(dx * rs * g2w[d0] + b2w[d0],
                            dy * rs * g2w[d0 + 1] + b2w[d0 + 1]);
    ((float2*)(out + ((size_t)(s * B_SZ + b)) * D_MODEL))[t] = ov;
}

// ---------------------------------------------------------------------------
// Launch
// ---------------------------------------------------------------------------
#define SMEM_BN128 (STAGES * (128 + 128) * 32 * 4)   // 98304
#define SMEM_BN64  (STAGES * (128 + 64) * 32 * 4)    // 73728

extern "C" void kernel_launch(void* const* d_in, const int* in_sizes, int n_in,
                              void* d_out, int out_size) {
    const float* src    = (const float*)d_in[0];
    const float* sph    = (const float*)d_in[1];
    const float* w_qs   = (const float*)d_in[2];
    const float* w_ks   = (const float*)d_in[3];
    const float* w_vs   = (const float*)d_in[4];
    const float* w_fc   = (const float*)d_in[5];
    const float* g_attn = (const float*)d_in[6];
    const float* b_attn = (const float*)d_in[7];
    const float* w1     = (const float*)d_in[8];
    const float* b1     = (const float*)d_in[9];
    const float* w2     = (const float*)d_in[10];
    const float* b2     = (const float*)d_in[11];
    const float* g1w    = (const float*)d_in[12];
    const float* bn1    = (const float*)d_in[13];
    const float* g2w    = (const float*)d_in[14];
    const float* bn2    = (const float*)d_in[15];

    float* out = (float*)d_out;
    float* p_out = out + OUT_ELEMS;

    void* sp = nullptr;
    cudaGetSymbolAddress(&sp, g_scratch);
    float* scr = (float*)sp;
    float* gq  = scr + OFF_Q;     // also base for K at +2M (EPI0 indexing)
    float* gao = scr + OFF_AO;
    float* gt1 = scr + OFF_T1;
    float* gh  = scr + OFF_H;
    float* gff = scr + OFF_FF;
    __half* vt_h = (__half*)(scr + OFF_VTH);
    __half* s_h  = (__half*)(scr + OFF_SH);
    __half* p_h  = (__half*)(scr + OFF_PH);

    cudaFuncSetAttribute(gemm_mma<0, 128, true>,
                         cudaFuncAttributeMaxDynamicSharedMemorySize, SMEM_BN128);
    cudaFuncSetAttribute(gemm_mma<2, 128, false>,
                         cudaFuncAttributeMaxDynamicSharedMemorySize, SMEM_BN128);
    cudaFuncSetAttribute(gemm_mma<4, 64, false>,
                         cudaFuncAttributeMaxDynamicSharedMemorySize, SMEM_BN64);
    cudaFuncSetAttribute(gemm_mma<5, 128, false>,
                         cudaFuncAttributeMaxDynamicSharedMemorySize, SMEM_BN128);
    cudaFuncSetAttribute(gemm_mma<6, 64, false>,
                         cudaFuncAttributeMaxDynamicSharedMemorySize, SMEM_BN64);

    // 1. fused QKV (reads src with permuted rows): z=0 Q, z=1 K, z=2 V^T fp16
    dim3 gqkv(D_MODEL / 128, M_ROWS / 128, 3);   // (4, 32, 3)
    gemm_mma<0, 128, true><<<gqkv, 256, SMEM_BN128>>>(
        src, D_MODEL, 0, w_qs, D_MODEL, 0, D_MODEL, gq, w_ks, w_vs, 0, vt_h);

    // 2. scores = (Q K^T) * 0.125 * sph  -> fp16 staging
    dim3 gsc(S_LEN / 128, S_LEN / 128, B_SZ * H_HEADS);  // (16, 16, 16)
    gemm_mma<2, 128, false><<<gsc, 256, SMEM_BN128>>>(
        gq, D_MODEL, 0, gq + 2097152, D_MODEL, 0, DK, nullptr, sph, nullptr, 0, s_h);

    // 3. softmax: fp16 in -> fp32 p_out + fp16 p_h
    softmax_rows<<<B_SZ * H_HEADS * S_LEN, 256>>>(s_h, p_out, p_h);

    // 4. O = P @ V  (fp16 MMA) -> gao model layout
    pv_f16<<<dim3(S_LEN / 128, B_SZ * H_HEADS), 256>>>(p_h, vt_h, gao);

    // 5. fc projection + residual(src perm)
    dim3 gfc(D_MODEL / 64, M_ROWS / 128, 1);             // (8, 32)
    gemm_mma<4, 64, false><<<gfc, 256, SMEM_BN64>>>(
        gao, D_MODEL, 0, w_fc, D_MODEL, 0, D_MODEL, gt1, src, nullptr, D_MODEL,
        nullptr);

    // 6. double LayerNorm
    ln_double_kernel<<<M_ROWS, 256>>>(gt1, src, g_attn, b_attn, g1w, bn1, gh);

    // 7. FFN up: relu(h @ w1^T + b1)
    dim3 gffn(F_FFN / 128, M_ROWS / 128, 1);             // (16, 32)
    gemm_mma<5, 128, false><<<gffn, 256, SMEM_BN128>>>(
        gh, D_MODEL, 0, w1, D_MODEL, 0, D_MODEL, gff, b1, nullptr, F_FFN, nullptr);

    // 8. FFN down + b2 + residual(h)
    gemm_mma<6, 64, false><<<gfc, 256, SMEM_BN64>>>(
        gff, F_FFN, 0, w2, F_FFN, 0, F_FFN, gt1, b2, gh, D_MODEL, nullptr);

    // 9. final LN + transposed store
    ln_final_kernel<<<M_ROWS, 256>>>(gt1, g2w, bn2, out);
}

// round 6
// speedup vs baseline: 6.9209x; 1.0667x over previous
#include <cuda_runtime.h>
#include <cuda_fp16.h>
#include <cstdint>
#include <cstddef>

// ---------------------------------------------------------------------------
// Problem constants
// ---------------------------------------------------------------------------
#define S_LEN 2048
#define B_SZ  2
#define D_MODEL 512
#define H_HEADS 8
#define DK 64
#define F_FFN 2048
#define M_ROWS (B_SZ * S_LEN)              // 4096
#define OUT_ELEMS (S_LEN * B_SZ * D_MODEL) // 2097152

// Scratch layout (float offsets)
#define OFF_AO  0
#define OFF_T1  2097152
#define OFF_H   4194304
#define OFF_FF  6291456                    // 8M floats
#define OFF_QH  14680064                   // fp16 Q (m,512): 2M halves = 1M floats
#define OFF_KH  15728640
#define OFF_VTH 16777216
#define OFF_SH  17825792                   // fp16 scores: 64M halves = 32M floats
#define OFF_PH  51380224
#define SCRATCH_FLOATS 84934656

__device__ float g_scratch[SCRATCH_FLOATS];

// ---------------------------------------------------------------------------
// PTX helpers
// ---------------------------------------------------------------------------
__device__ __forceinline__ uint32_t smem_to_u32(const void* p) {
    uint32_t a;
    asm("{ .reg .u64 t; cvta.to.shared.u64 t, %1; cvt.u32.u64 %0, t; }"
        : "=r"(a) : "l"(p));
    return a;
}

#define CP_ASYNC16(dst, src) \
    asm volatile("cp.async.cg.shared.global [%0], [%1], 16;\n" \
                 :: "r"(dst), "l"(src))
#define CP_COMMIT() asm volatile("cp.async.commit_group;\n" ::: "memory")
#define CP_WAIT1()  asm volatile("cp.async.wait_group 1;\n" ::: "memory")
#define CP_WAIT0()  asm volatile("cp.async.wait_group 0;\n" ::: "memory")

__device__ __forceinline__ void mma_tf32(float (&dd)[4], const uint32_t (&a)[4],
                                         const uint32_t (&b)[2]) {
    asm volatile(
        "mma.sync.aligned.m16n8k8.row.col.f32.tf32.tf32.f32 "
        "{%0,%1,%2,%3}, {%4,%5,%6,%7}, {%8,%9}, {%0,%1,%2,%3};\n"
        : "+f"(dd[0]), "+f"(dd[1]), "+f"(dd[2]), "+f"(dd[3])
        : "r"(a[0]), "r"(a[1]), "r"(a[2]), "r"(a[3]), "r"(b[0]), "r"(b[1]));
}

__device__ __forceinline__ void mma_f16(float (&dd)[4], const uint32_t (&a)[4],
                                        const uint32_t (&b)[2]) {
    asm volatile(
        "mma.sync.aligned.m16n8k16.row.col.f32.f16.f16.f32 "
        "{%0,%1,%2,%3}, {%4,%5,%6,%7}, {%8,%9}, {%0,%1,%2,%3};\n"
        : "+f"(dd[0]), "+f"(dd[1]), "+f"(dd[2]), "+f"(dd[3])
        : "r"(a[0]), "r"(a[1]), "r"(a[2]), "r"(a[3]), "r"(b[0]), "r"(b[1]));
}

// permuted src row: x[m] = src[(s*B + b)] with m = b*S + s
__device__ __forceinline__ int perm_row(int m) {
    return ((m & (S_LEN - 1)) << 1) + (m >> 11);
}

// ---------------------------------------------------------------------------
// tf32 mma.sync GEMM: BM=128, BN template, BK=32, 3-stage cp.async ring.
// EPI: 0 = fused QKV (APERM; z=0 Q fp16, z=1 K fp16, z=2 V^T fp16 scatter)
//      4 = +resid(src perm)   5 = +bias,relu   6 = +bias +resid
// ---------------------------------------------------------------------------
#define STAGES 3

template <int EPI, int BN, bool APERM>
__global__ void __launch_bounds__(256, 2) gemm_mma(
    const float* __restrict__ A, int lda, long long aZ,
    const float* __restrict__ Bw, int ldb, long long bZ,
    int K, float* __restrict__ C,
    const float* __restrict__ aux1, const float* __restrict__ aux2, int ldc,
    __half* __restrict__ Chalf) {
    constexpr int NT = BN / 16;
    extern __shared__ float dsm[];
    float* smA = dsm;
    float* smB = dsm + STAGES * 128 * 32;

    const int tid = threadIdx.x;
    const int w = tid >> 5, lane = tid & 31;
    const int g = lane >> 2, t = lane & 3;
    const int mw = w >> 1, nw = w & 1;
    const int m0 = blockIdx.y * 128, n0 = blockIdx.x * BN;
    const int z = blockIdx.z;

    const float* Bp;
    if (EPI == 0) {
        Bp = (z == 0) ? Bw : (z == 1) ? aux1 : aux2;
    } else {
        A += (size_t)z * aZ;
        Bp = Bw + (size_t)z * bZ;
    }

    const uint32_t sA = smem_to_u32(smA);
    const uint32_t sB = smem_to_u32(smB);

    float d[2][NT][4];
#pragma unroll
    for (int i = 0; i < 2; i++)
#pragma unroll
        for (int j = 0; j < NT; j++)
#pragma unroll
            for (int r = 0; r < 4; r++) d[i][j][r] = 0.f;

    const int NC = K >> 5;

    auto issue = [&](int kc, int stg) {
        int k0 = kc << 5;
#pragma unroll
        for (int i = 0; i < 4; i++) {
            int id = tid + (i << 8);
            int r = id >> 3, q = id & 7;
            uint32_t dst = sA + ((stg * 4096 + r * 32 + ((q ^ (r & 7)) << 2)) << 2);
            int gr = m0 + r;
            const float* srcp = A + (size_t)(APERM ? perm_row(gr) : gr) * lda +
                                k0 + (q << 2);
            CP_ASYNC16(dst, srcp);
        }
#pragma unroll
        for (int i = 0; i < BN / 32; i++) {
            int id = tid + (i << 8);
            int r = id >> 3, q = id & 7;
            uint32_t dst = sB + ((stg * (BN * 32) + r * 32 + ((q ^ (r & 7)) << 2)) << 2);
            CP_ASYNC16(dst, Bp + (size_t)(n0 + r) * ldb + k0 + (q << 2));
        }
        CP_COMMIT();
    };

    issue(0, 0);
    if (NC > 1) issue(1, 1);

    for (int kc = 0; kc < NC; kc++) {
        if (kc == NC - 1) { CP_WAIT0(); } else { CP_WAIT1(); }
        __syncthreads();
        if (kc + 2 < NC) issue(kc + 2, (kc + 2) % STAGES);

        int buf = kc % STAGES;
        const float* Ab = smA + buf * 4096;
        const float* Bb = smB + buf * (BN * 32);
#pragma unroll
        for (int ks = 0; ks < 4; ks++) {
            const int pc0 = (((2 * ks) ^ g) << 2) + t;
            const int pc1 = (((2 * ks + 1) ^ g) << 2) + t;
            uint32_t a[2][4];
#pragma unroll
            for (int mtw = 0; mtw < 2; mtw++) {
                int row = (mw * 2 + mtw) * 16 + g;
                a[mtw][0] = __float_as_uint(Ab[row * 32 + pc0]);
                a[mtw][1] = __float_as_uint(Ab[(row + 8) * 32 + pc0]);
                a[mtw][2] = __float_as_uint(Ab[row * 32 + pc1]);
                a[mtw][3] = __float_as_uint(Ab[(row + 8) * 32 + pc1]);
            }
            uint32_t b[NT][2];
#pragma unroll
            for (int ntw = 0; ntw < NT; ntw++) {
                int nr = (nw * NT + ntw) * 8 + g;
                b[ntw][0] = __float_as_uint(Bb[nr * 32 + pc0]);
                b[ntw][1] = __float_as_uint(Bb[nr * 32 + pc1]);
            }
#pragma unroll
            for (int mtw = 0; mtw < 2; mtw++)
#pragma unroll
                for (int ntw = 0; ntw < NT; ntw++)
                    mma_tf32(d[mtw][ntw], a[mtw], b[ntw]);
        }
        __syncthreads();
    }

    // ---------------- epilogue ----------------
#pragma unroll
    for (int mtw = 0; mtw < 2; mtw++)
#pragma unroll
        for (int ntw = 0; ntw < NT; ntw++)
#pragma unroll
            for (int half = 0; half < 2; half++) {
                int m = m0 + mw * 32 + mtw * 16 + half * 8 + g;
                int n = n0 + nw * (BN / 2) + ntw * 8 + t * 2;
                float v0 = d[mtw][ntw][half * 2 + 0];
                float v1 = d[mtw][ntw][half * 2 + 1];
                if (EPI == 0) {
                    if (z < 2) {          // Q/K fp16 plain (m, 512)
                        __half* dst = Chalf + (size_t)z * 2097152 +
                                      (size_t)m * D_MODEL + n;
                        *(__half2*)dst = __floats2half2_rn(v0, v1);
                    } else {              // V^T fp16 scatter to (b,h,dk,s)
                        int b = m >> 11, s = m & (S_LEN - 1);
                        int h = n >> 6, dd = n & 63;
                        __half* vt = Chalf + 2 * 2097152;
                        size_t base = ((size_t)((b << 3) + h) * DK + dd) * S_LEN + s;
                        vt[base] = __float2half(v0);
                        vt[base + S_LEN] = __float2half(v1);
                    }
                } else if (EPI == 4) {    // + resid (src, perm)
                    size_t o = (size_t)m * ldc + n;
                    const float* rsrc = aux1 + (size_t)perm_row(m) * D_MODEL + n;
                    float2 rr = *(const float2*)rsrc;
                    *(float2*)(C + o) = make_float2(v0 + rr.x, v1 + rr.y);
                } else if (EPI == 5) {    // + bias, relu
                    size_t o = (size_t)m * ldc + n;
                    float2 bb = *(const float2*)(aux1 + n);
                    *(float2*)(C + o) = make_float2(fmaxf(v0 + bb.x, 0.f),
                                                    fmaxf(v1 + bb.y, 0.f));
                } else {                  // + bias + resid
                    size_t o = (size_t)m * ldc + n;
                    float2 bb = *(const float2*)(aux1 + n);
                    float2 rr = *(const float2*)(aux2 + o);
                    *(float2*)(C + o) = make_float2(v0 + bb.x + rr.x,
                                                    v1 + bb.y + rr.y);
                }
            }
}

// ---------------------------------------------------------------------------
// Scores (fp16 x fp16): S[bh](m,n) = (Q K^T)(m,n) * 0.125 * sph -> fp16
// BM=BN=128, K=64 (single stage), 256 threads, 128B smem rows (conflict-free).
// ---------------------------------------------------------------------------
__global__ void __launch_bounds__(256, 2) scores_f16(
    const __half* __restrict__ qh, const __half* __restrict__ kh,
    const float* __restrict__ sph, __half* __restrict__ s_h) {
    __shared__ __half sAm[128 * 64];
    __shared__ __half sBm[128 * 64];

    const int tid = threadIdx.x;
    const int w = tid >> 5, lane = tid & 31;
    const int g = lane >> 2, t = lane & 3;
    const int mw = w >> 1, nw = w & 1;
    const int m0 = blockIdx.y * 128, n0 = blockIdx.x * 128;
    const int bh = blockIdx.z;

    size_t hoff = (size_t)(bh >> 3) * (S_LEN * D_MODEL) + (size_t)(bh & 7) * DK;
    const __half* Ap = qh + hoff;
    const __half* Bp = kh + hoff;

    const uint32_t sA = smem_to_u32(sAm);
    const uint32_t sB = smem_to_u32(sBm);

#pragma unroll
    for (int i = 0; i < 4; i++) {
        int id = tid + (i << 8);
        int r = id >> 3, c = id & 7;
        uint32_t dst = sA + ((r * 64 + ((c ^ (r & 7)) << 3)) << 1);
        CP_ASYNC16(dst, Ap + (size_t)(m0 + r) * D_MODEL + (c << 3));
    }
#pragma unroll
    for (int i = 0; i < 4; i++) {
        int id = tid + (i << 8);
        int r = id >> 3, c = id & 7;
        uint32_t dst = sB + ((r * 64 + ((c ^ (r & 7)) << 3)) << 1);
        CP_ASYNC16(dst, Bp + (size_t)(n0 + r) * D_MODEL + (c << 3));
    }
    CP_COMMIT();
    CP_WAIT0();
    __syncthreads();

    float d[2][8][4];
#pragma unroll
    for (int i = 0; i < 2; i++)
#pragma unroll
        for (int j = 0; j < 8; j++)
#pragma unroll
            for (int r = 0; r < 4; r++) d[i][j][r] = 0.f;

#pragma unroll
    for (int ks = 0; ks < 4; ks++) {
        const int lo = ((2 * ks) ^ g) * 8 + 2 * t;
        const int hi = ((2 * ks + 1) ^ g) * 8 + 2 * t;
        uint32_t a[2][4];
#pragma unroll
        for (int mtw = 0; mtw < 2; mtw++) {
            int r0 = (mw * 2 + mtw) * 16 + g;
            a[mtw][0] = *(const uint32_t*)(sAm + r0 * 64 + lo);
            a[mtw][1] = *(const uint32_t*)(sAm + (r0 + 8) * 64 + lo);
            a[mtw][2] = *(const uint32_t*)(sAm + r0 * 64 + hi);
            a[mtw][3] = *(const uint32_t*)(sAm + (r0 + 8) * 64 + hi);
        }
        uint32_t b[8][2];
#pragma unroll
        for (int ntw = 0; ntw < 8; ntw++) {
            int nr = nw * 64 + ntw * 8 + g;
            b[ntw][0] = *(const uint32_t*)(sBm + nr * 64 + lo);
            b[ntw][1] = *(const uint32_t*)(sBm + nr * 64 + hi);
        }
#pragma unroll
        for (int mtw = 0; mtw < 2; mtw++)
#pragma unroll
            for (int ntw = 0; ntw < 8; ntw++)
                mma_f16(d[mtw][ntw], a[mtw], b[ntw]);
    }

#pragma unroll
    for (int mtw = 0; mtw < 2; mtw++)
#pragma unroll
        for (int ntw = 0; ntw < 8; ntw++)
#pragma unroll
            for (int half = 0; half < 2; half++) {
                int m = m0 + mw * 32 + mtw * 16 + half * 8 + g;
                int n = n0 + nw * 64 + ntw * 8 + t * 2;
                size_t idx = ((size_t)bh * S_LEN + m) * S_LEN + n;
                float2 sp = *(const float2*)(sph + idx);
                float v0 = d[mtw][ntw][half * 2 + 0] * 0.125f * sp.x;
                float v1 = d[mtw][ntw][half * 2 + 1] * 0.125f * sp.y;
                *(__half2*)(s_h + idx) = __floats2half2_rn(v0, v1);
            }
}

// ---------------------------------------------------------------------------
// Fused softmax + PV. One CTA: 64 q-rows of one (b,h).
// Pass 1: rows in registers -> max/exp/sum -> write fp32 p_attn + fp16 p_h.
// Pass 2: O = P @ V^T (fp16 mma, BK=64, double-buffered), scatter to gao.
// ---------------------------------------------------------------------------
__global__ void __launch_bounds__(256) softmax_pv(
    const __half* __restrict__ s_h, float* __restrict__ p_out,
    __half* __restrict__ p_h, const __half* __restrict__ vt,
    float* __restrict__ gao) {
    __shared__ __half smA[2][64 * 64];   // 8KB each
    __shared__ __half smB[2][64 * 64];

    const int tid = threadIdx.x;
    const int w = tid >> 5, lane = tid & 31;
    const int bh = blockIdx.y;
    const int m0 = blockIdx.x * 64;

    // ---------------- pass 1: softmax ----------------
    {
        const __half* srow0 = s_h + ((size_t)bh * S_LEN + m0) * S_LEN;
        float* prow0 = p_out + ((size_t)bh * S_LEN + m0) * S_LEN;
        __half* phrow0 = p_h + ((size_t)bh * S_LEN + m0) * S_LEN;
        for (int rr = 0; rr < 8; rr++) {
            int r = w * 8 + rr;
            const uint4* srcp = (const uint4*)(srow0 + (size_t)r * S_LEN) + lane;
            float ex[64];
#pragma unroll
            for (int it = 0; it < 8; it++) {
                uint4 v = srcp[it * 32];
                const __half2* hp = (const __half2*)&v;
#pragma unroll
                for (int j = 0; j < 4; j++) {
                    float2 f = __half22float2(hp[j]);
                    ex[it * 8 + 2 * j] = f.x;
                    ex[it * 8 + 2 * j + 1] = f.y;
                }
            }
            float mx = -1e30f;
#pragma unroll
            for (int i = 0; i < 64; i++) mx = fmaxf(mx, ex[i]);
#pragma unroll
            for (int o = 16; o; o >>= 1)
                mx = fmaxf(mx, __shfl_xor_sync(0xffffffffu, mx, o));
            float sum = 0.f;
#pragma unroll
            for (int i = 0; i < 64; i++) {
                ex[i] = __expf(ex[i] - mx);
                sum += ex[i];
            }
#pragma unroll
            for (int o = 16; o; o >>= 1)
                sum += __shfl_xor_sync(0xffffffffu, sum, o);
            float inv = 1.0f / sum;

            float* prow = prow0 + (size_t)r * S_LEN;
            __half* phrow = phrow0 + (size_t)r * S_LEN;
#pragma unroll
            for (int it = 0; it < 8; it++) {
                int base = (it * 32 + lane) * 8;
                float p0 = ex[it * 8 + 0] * inv, p1 = ex[it * 8 + 1] * inv;
                float p2 = ex[it * 8 + 2] * inv, p3 = ex[it * 8 + 3] * inv;
                float p4 = ex[it * 8 + 4] * inv, p5 = ex[it * 8 + 5] * inv;
                float p6 = ex[it * 8 + 6] * inv, p7 = ex[it * 8 + 7] * inv;
                *(float4*)(prow + base) = make_float4(p0, p1, p2, p3);
                *(float4*)(prow + base + 4) = make_float4(p4, p5, p6, p7);
                uint4 pk;
                __half2* pk2 = (__half2*)&pk;
                pk2[0] = __floats2half2_rn(p0, p1);
                pk2[1] = __floats2half2_rn(p2, p3);
                pk2[2] = __floats2half2_rn(p4, p5);
                pk2[3] = __floats2half2_rn(p6, p7);
                *(uint4*)(phrow + base) = pk;
            }
        }
    }
    __threadfence_block();
    __syncthreads();

    // ---------------- pass 2: PV ----------------
    const int g = lane >> 2, t = lane & 3;
    const int mw = w >> 1, nw = w & 1;

    const __half* Ap = p_h + ((size_t)bh * S_LEN + m0) * S_LEN;
    const __half* Bp = vt + (size_t)bh * DK * S_LEN;
    const uint32_t sA = smem_to_u32(smA);
    const uint32_t sB = smem_to_u32(smB);

    float d[4][4];
#pragma unroll
    for (int j = 0; j < 4; j++)
#pragma unroll
        for (int r = 0; r < 4; r++) d[j][r] = 0.f;

    const int NC = S_LEN / 64;   // 32 chunks of 64 halves

    auto issue = [&](int kc, int stg) {
        int k0 = kc << 6;
#pragma unroll
        for (int i = 0; i < 2; i++) {
            int id = tid + (i << 8);          // 64 rows x 8 chunks = 512
            int r = id >> 3, c = id & 7;
            uint32_t dst = sA + ((stg * 4096 + r * 64 + ((c ^ (r & 7)) << 3)) << 1);
            CP_ASYNC16(dst, Ap + (size_t)r * S_LEN + k0 + (c << 3));
        }
#pragma unroll
        for (int i = 0; i < 2; i++) {
            int id = tid + (i << 8);
            int r = id >> 3, c = id & 7;
            uint32_t dst = sB + ((stg * 4096 + r * 64 + ((c ^ (r & 7)) << 3)) << 1);
            CP_ASYNC16(dst, Bp + (size_t)r * S_LEN + k0 + (c << 3));
        }
        CP_COMMIT();
    };

    issue(0, 0);
    for (int kc = 0; kc < NC; kc++) {
        if (kc + 1 < NC) {
            issue(kc + 1, (kc + 1) & 1);
            CP_WAIT1();
        } else {
            CP_WAIT0();
        }
        __syncthreads();
        int buf = kc & 1;
        const __half* Ab = smA[buf];
        const __half* Bb = smB[buf];
#pragma unroll
        for (int ks = 0; ks < 4; ks++) {
            const int lo = ((2 * ks) ^ g) * 8 + 2 * t;
            const int hi = ((2 * ks + 1) ^ g) * 8 + 2 * t;
            uint32_t a[4];
            {
                int r0 = mw * 16 + g;
                a[0] = *(const uint32_t*)(Ab + r0 * 64 + lo);
                a[1] = *(const uint32_t*)(Ab + (r0 + 8) * 64 + lo);
                a[2] = *(const uint32_t*)(Ab + r0 * 64 + hi);
                a[3] = *(const uint32_t*)(Ab + (r0 + 8) * 64 + hi);
            }
            uint32_t b[4][2];
#pragma unroll
            for (int ntw = 0; ntw < 4; ntw++) {
                int nr = nw * 32 + ntw * 8 + g;
                b[ntw][0] = *(const uint32_t*)(Bb + nr * 64 + lo);
                b[ntw][1] = *(const uint32_t*)(Bb + nr * 64 + hi);
            }
#pragma unroll
            for (int ntw = 0; ntw < 4; ntw++)
                mma_f16(d[ntw], a, b[ntw]);
        }
        __syncthreads();
    }

    int b = bh >> 3, h = bh & 7;
#pragma unroll
    for (int ntw = 0; ntw < 4; ntw++)
#pragma unroll
        for (int half = 0; half < 2; half++) {
            int m = m0 + mw * 16 + half * 8 + g;
            int n = nw * 32 + ntw * 8 + t * 2;
            size_t dst = ((size_t)(b * S_LEN + m)) * D_MODEL + h * DK + n;
            *(float2*)(gao + dst) = make_float2(d[ntw][half * 2 + 0],
                                                d[ntw][half * 2 + 1]);
        }
}

// ---------------------------------------------------------------------------
// LayerNorm kernels
// ---------------------------------------------------------------------------
__device__ __forceinline__ float blockSum256(float v, float* sred) {
#pragma unroll
    for (int o = 16; o; o >>= 1) v += __shfl_xor_sync(0xffffffffu, v, o);
    __syncthreads();
    if ((threadIdx.x & 31) == 0) sred[threadIdx.x >> 5] = v;
    __syncthreads();
    float s = sred[0];
#pragma unroll
    for (int i = 1; i < 8; i++) s += sred[i];
    return s;
}

__global__ void __launch_bounds__(256) ln_double_kernel(
    const float* __restrict__ tin, const float* __restrict__ src,
    const float* __restrict__ ga, const float* __restrict__ ba,
    const float* __restrict__ g1w, const float* __restrict__ b1w,
    float* __restrict__ hout) {
    __shared__ float sred[8];
    int m = blockIdx.x, t = threadIdx.x;
    float2 v = ((const float2*)(tin + (size_t)m * D_MODEL))[t];
    float2 xv = ((const float2*)(src + (size_t)perm_row(m) * D_MODEL))[t];
    float mu = blockSum256(v.x + v.y, sred) * (1.f / 512.f);
    float dx = v.x - mu, dy = v.y - mu;
    float var = blockSum256(dx * dx + dy * dy, sred) * (1.f / 512.f);
    float rs = rsqrtf(var + 1e-6f);
    int d0 = t * 2;
    float u0 = xv.x + dx * rs * ga[d0] + ba[d0];
    float u1 = xv.y + dy * rs * ga[d0 + 1] + ba[d0 + 1];
    mu = blockSum256(u0 + u1, sred) * (1.f / 512.f);
    dx = u0 - mu; dy = u1 - mu;
    var = blockSum256(dx * dx + dy * dy, sred) * (1.f / 512.f);
    rs = rsqrtf(var + 1e-5f);
    float2 hv = make_float2(dx * rs * g1w[d0] + b1w[d0],
                            dy * rs * g1w[d0 + 1] + b1w[d0 + 1]);
    ((float2*)(hout + (size_t)m * D_MODEL))[t] = hv;
}

__global__ void __launch_bounds__(256) ln_final_kernel(
    const float* __restrict__ tin, const float* __restrict__ g2w,
    const float* __restrict__ b2w, float* __restrict__ out) {
    __shared__ float sred[8];
    int m = blockIdx.x, t = threadIdx.x;
    float2 v = ((const float2*)(tin + (size_t)m * D_MODEL))[t];
    float mu = blockSum256(v.x + v.y, sred) * (1.f / 512.f);
    float dx = v.x - mu, dy = v.y - mu;
    float var = blockSum256(dx * dx + dy * dy, sred) * (1.f / 512.f);
    float rs = rsqrtf(var + 1e-5f);
    int d0 = t * 2;
    int b = m >> 11;
    int s = m & (S_LEN - 1);
    float2 ov = make_float2(dx * rs * g2w[d0] + b2w[d0],
                            dy * rs * g2w[d0 + 1] + b2w[d0 + 1]);
    ((float2*)(out + ((size_t)(s * B_SZ + b)) * D_MODEL))[t] = ov;
}

// ---------------------------------------------------------------------------
// Launch
// ---------------------------------------------------------------------------
#define SMEM_BN128 (STAGES * (128 + 128) * 32 * 4)   // 98304
#define SMEM_BN64  (STAGES * (128 + 64) * 32 * 4)    // 73728

extern "C" void kernel_launch(void* const* d_in, const int* in_sizes, int n_in,
                              void* d_out, int out_size) {
    const float* src    = (const float*)d_in[0];
    const float* sph    = (const float*)d_in[1];
    const float* w_qs   = (const float*)d_in[2];
    const float* w_ks   = (const float*)d_in[3];
    const float* w_vs   = (const float*)d_in[4];
    const float* w_fc   = (const float*)d_in[5];
    const float* g_attn = (const float*)d_in[6];
    const float* b_attn = (const float*)d_in[7];
    const float* w1     = (const float*)d_in[8];
    const float* b1     = (const float*)d_in[9];
    const float* w2     = (const float*)d_in[10];
    const float* b2     = (const float*)d_in[11];
    const float* g1w    = (const float*)d_in[12];
    const float* bn1    = (const float*)d_in[13];
    const float* g2w    = (const float*)d_in[14];
    const float* bn2    = (const float*)d_in[15];

    float* out = (float*)d_out;
    float* p_out = out + OUT_ELEMS;

    void* sp = nullptr;
    cudaGetSymbolAddress(&sp, g_scratch);
    float* scr = (float*)sp;
    float* gao = scr + OFF_AO;
    float* gt1 = scr + OFF_T1;
    float* gh  = scr + OFF_H;
    float* gff = scr + OFF_FF;
    __half* qh   = (__half*)(scr + OFF_QH);
    __half* kh   = (__half*)(scr + OFF_KH);
    __half* vt_h = (__half*)(scr + OFF_VTH);
    __half* s_h  = (__half*)(scr + OFF_SH);
    __half* p_h  = (__half*)(scr + OFF_PH);

    cudaFuncSetAttribute(gemm_mma<0, 128, true>,
                         cudaFuncAttributeMaxDynamicSharedMemorySize, SMEM_BN128);
    cudaFuncSetAttribute(gemm_mma<4, 64, false>,
                         cudaFuncAttributeMaxDynamicSharedMemorySize, SMEM_BN64);
    cudaFuncSetAttribute(gemm_mma<5, 128, false>,
                         cudaFuncAttributeMaxDynamicSharedMemorySize, SMEM_BN128);
    cudaFuncSetAttribute(gemm_mma<6, 64, false>,
                         cudaFuncAttributeMaxDynamicSharedMemorySize, SMEM_BN64);

    // 1. fused QKV (perm-read src): z=0 Q fp16, z=1 K fp16, z=2 V^T fp16
    dim3 gqkv(D_MODEL / 128, M_ROWS / 128, 3);   // (4, 32, 3)
    gemm_mma<0, 128, true><<<gqkv, 256, SMEM_BN128>>>(
        src, D_MODEL, 0, w_qs, D_MODEL, 0, D_MODEL, nullptr, w_ks, w_vs, 0, qh);

    // 2. scores = (Q K^T) * 0.125 * sph  -> fp16 staging (fp16 MMA)
    dim3 gsc(S_LEN / 128, S_LEN / 128, B_SZ * H_HEADS);  // (16, 16, 16)
    scores_f16<<<gsc, 256>>>(qh, kh, sph, s_h);

    // 3. fused softmax + PV -> p_out (fp32) and gao
    softmax_pv<<<dim3(S_LEN / 64, B_SZ * H_HEADS), 256>>>(s_h, p_out, p_h,
                                                          vt_h, gao);

    // 4. fc projection + residual(src perm)
    dim3 gfc(D_MODEL / 64, M_ROWS / 128, 1);             // (8, 32)
    gemm_mma<4, 64, false><<<gfc, 256, SMEM_BN64>>>(
        gao, D_MODEL, 0, w_fc, D_MODEL, 0, D_MODEL, gt1, src, nullptr, D_MODEL,
        nullptr);

    // 5. double LayerNorm
    ln_double_kernel<<<M_ROWS, 256>>>(gt1, src, g_attn, b_attn, g1w, bn1, gh);

    // 6. FFN up: relu(h @ w1^T + b1)
    dim3 gffn(F_FFN / 128, M_ROWS / 128, 1);             // (16, 32)
    gemm_mma<5, 128, false><<<gffn, 256, SMEM_BN128>>>(
        gh, D_MODEL, 0, w1, D_MODEL, 0, D_MODEL, gff, b1, nullptr, F_FFN, nullptr);

    // 7. FFN down + b2 + residual(h)
    gemm_mma<6, 64, false><<<gfc, 256, SMEM_BN64>>>(
        gff, F_FFN, 0, w2, F_FFN, 0, F_FFN, gt1, b2, gh, D_MODEL, nullptr);

    // 8. final LN + transposed store
    ln_final_kernel<<<M_ROWS, 256>>>(gt1, g2w, bn2, out);
}

// round 8
// speedup vs baseline: 8.3070x; 1.2003x over previous
#include <cuda_runtime.h>
#include <cuda_fp16.h>
#include <cstdint>
#include <cstddef>

// ---------------------------------------------------------------------------
// Problem constants
// ---------------------------------------------------------------------------
#define S_LEN 2048
#define B_SZ  2
#define D_MODEL 512
#define H_HEADS 8
#define DK 64
#define F_FFN 2048
#define M_ROWS (B_SZ * S_LEN)              // 4096
#define OUT_ELEMS (S_LEN * B_SZ * D_MODEL) // 2097152

// Scratch layout (float offsets)
#define OFF_T1   0                         // 2M floats
#define OFF_H    2097152                   // 2M floats
#define OFF_XH   4194304                   // 2M halves = 1M floats
#define OFF_QH   5242880                   // Q,K,VT each 2M halves = 1M floats
#define OFF_KH   6291456
#define OFF_VTH  7340032
#define OFF_GAOH 8388608                   // 1M floats
#define OFF_HH   9437184                   // 1M floats
#define OFF_FFH  10485760                  // 8M halves = 4M floats
#define OFF_WQH  14680064                  // 128K floats each
#define OFF_WKH  14811136
#define OFF_WVH  14942208
#define OFF_WFCH 15073280
#define OFF_W1H  15204352                  // 512K floats
#define OFF_W2H  15728640                  // 512K floats
#define OFF_SH   16252928                  // 67108864 halves = 33554432 floats
#define OFF_PH   49807360                  // 67108864 halves = 33554432 floats
#define SCRATCH_FLOATS 83361792

__device__ float g_scratch[SCRATCH_FLOATS];

// ---------------------------------------------------------------------------
// PTX helpers
// ---------------------------------------------------------------------------
__device__ __forceinline__ uint32_t smem_to_u32(const void* p) {
    uint32_t a;
    asm("{ .reg .u64 t; cvta.to.shared.u64 t, %1; cvt.u32.u64 %0, t; }"
        : "=r"(a) : "l"(p));
    return a;
}

#define CP_ASYNC16(dst, src) \
    asm volatile("cp.async.cg.shared.global [%0], [%1], 16;\n" \
                 :: "r"(dst), "l"(src))
#define CP_COMMIT() asm volatile("cp.async.commit_group;\n" ::: "memory")
#define CP_WAIT1()  asm volatile("cp.async.wait_group 1;\n" ::: "memory")
#define CP_WAIT0()  asm volatile("cp.async.wait_group 0;\n" ::: "memory")

__device__ __forceinline__ void mma_f16(float (&dd)[4], const uint32_t (&a)[4],
                                        const uint32_t (&b)[2]) {
    asm volatile(
        "mma.sync.aligned.m16n8k16.row.col.f32.f16.f16.f32 "
        "{%0,%1,%2,%3}, {%4,%5,%6,%7}, {%8,%9}, {%0,%1,%2,%3};\n"
        : "+f"(dd[0]), "+f"(dd[1]), "+f"(dd[2]), "+f"(dd[3])
        : "r"(a[0]), "r"(a[1]), "r"(a[2]), "r"(a[3]), "r"(b[0]), "r"(b[1]));
}

// permuted src row: x[m] = src[(s*B + b)] with m = b*S + s
__device__ __forceinline__ int perm_row(int m) {
    return ((m & (S_LEN - 1)) << 1) + (m >> 11);
}

// ---------------------------------------------------------------------------
// Conversion prep: src (permuted) + 6 weight matrices -> fp16
// ---------------------------------------------------------------------------
__global__ void __launch_bounds__(256) convert_all(
    const float* __restrict__ src,
    const float* __restrict__ wq, const float* __restrict__ wk,
    const float* __restrict__ wv, const float* __restrict__ wfc,
    const float* __restrict__ w1, const float* __restrict__ w2,
    __half* __restrict__ xh, __half* __restrict__ wqh, __half* __restrict__ wkh,
    __half* __restrict__ wvh, __half* __restrict__ wfch,
    __half* __restrict__ w1h, __half* __restrict__ w2h) {
    int i4 = blockIdx.x * 256 + threadIdx.x;   // float4 index
    if (i4 < 524288) {                          // xh with row permutation
        int m = i4 >> 7;
        int c = (i4 & 127) << 2;
        float4 v = *(const float4*)(src + (size_t)perm_row(m) * D_MODEL + c);
        __half2* d = (__half2*)(xh + (size_t)m * D_MODEL + c);
        d[0] = __floats2half2_rn(v.x, v.y);
        d[1] = __floats2half2_rn(v.z, v.w);
        return;
    }
    i4 -= 524288;
    const float* sp;
    __half* dp;
    if (i4 < 65536) { sp = wq; dp = wqh; }
    else if (i4 < 131072) { sp = wk; dp = wkh; i4 -= 65536; }
    else if (i4 < 196608) { sp = wv; dp = wvh; i4 -= 131072; }
    else if (i4 < 262144) { sp = wfc; dp = wfch; i4 -= 196608; }
    else if (i4 < 524288) { sp = w1; dp = w1h; i4 -= 262144; }
    else { sp = w2; dp = w2h; i4 -= 524288; }
    float4 v = *(const float4*)(sp + (size_t)i4 * 4);
    __half2* d = (__half2*)(dp + (size_t)i4 * 4);
    d[0] = __floats2half2_rn(v.x, v.y);
    d[1] = __floats2half2_rn(v.z, v.w);
}

// ---------------------------------------------------------------------------
// fp16 mma.sync GEMM: C[m,n] = sum_k A[m,k] * Bw[n,k]  (K-major halves)
// BM=128, BN template, BK=64, 3-stage cp.async ring, 256 threads (4m x 2n),
// 128-byte smem rows with conflict-free 8-chunk XOR swizzle.
//
// EPI: 0 = fused QKV (z selects B: B0/B1/B2; z<2 plain fp16, z=2 V^T scatter)
//      4 = fp32 out + resid(src perm)
//      5 = fp16 out relu(v + bias)
//      6 = fp32 out + bias + resid(fp32)
// ---------------------------------------------------------------------------
#define STAGES 3

template <int EPI, int BN>
__global__ void __launch_bounds__(256, 2) gemm_h(
    const __half* __restrict__ A, int lda,
    const __half* __restrict__ B0, const __half* __restrict__ B1,
    const __half* __restrict__ B2, int ldb,
    int K, float* __restrict__ C,
    const float* __restrict__ bias, const float* __restrict__ resid,
    int ldc, __half* __restrict__ Chalf) {
    constexpr int NT = BN / 16;
    constexpr int ASTG = 128 * 64;           // halves per A stage
    constexpr int BSTG = BN * 64;
    extern __shared__ __half hsm[];
    __half* smA = hsm;
    __half* smB = hsm + STAGES * ASTG;

    const int tid = threadIdx.x;
    const int w = tid >> 5, lane = tid & 31;
    const int g = lane >> 2, t = lane & 3;
    const int mw = w >> 1, nw = w & 1;
    const int m0 = blockIdx.y * 128, n0 = blockIdx.x * BN;
    const int z = blockIdx.z;

    const __half* Bp = (EPI == 0) ? ((z == 0) ? B0 : (z == 1) ? B1 : B2) : B0;

    const uint32_t sA = smem_to_u32(smA);
    const uint32_t sB = smem_to_u32(smB);

    float d[2][NT][4];
#pragma unroll
    for (int i = 0; i < 2; i++)
#pragma unroll
        for (int j = 0; j < NT; j++)
#pragma unroll
            for (int r = 0; r < 4; r++) d[i][j][r] = 0.f;

    const int NC = K >> 6;

    auto issue = [&](int kc, int stg) {
        int k0 = kc << 6;
#pragma unroll
        for (int i = 0; i < 4; i++) {
            int id = tid + (i << 8);          // 128 rows x 8 chunks
            int r = id >> 3, c = id & 7;
            uint32_t dst = sA + ((stg * ASTG + r * 64 + ((c ^ (r & 7)) << 3)) << 1);
            CP_ASYNC16(dst, A + (size_t)(m0 + r) * lda + k0 + (c << 3));
        }
#pragma unroll
        for (int i = 0; i < BN / 32; i++) {
            int id = tid + (i << 8);
            int r = id >> 3, c = id & 7;
            uint32_t dst = sB + ((stg * BSTG + r * 64 + ((c ^ (r & 7)) << 3)) << 1);
            CP_ASYNC16(dst, Bp + (size_t)(n0 + r) * ldb + k0 + (c << 3));
        }
        CP_COMMIT();
    };

    issue(0, 0);
    if (NC > 1) issue(1, 1);

    for (int kc = 0; kc < NC; kc++) {
        if (kc == NC - 1) { CP_WAIT0(); } else { CP_WAIT1(); }
        __syncthreads();
        if (kc + 2 < NC) issue(kc + 2, (kc + 2) % STAGES);

        int buf = kc % STAGES;
        const __half* Ab = smA + buf * ASTG;
        const __half* Bb = smB + buf * BSTG;
#pragma unroll
        for (int ks = 0; ks < 4; ks++) {
            const int lo = ((2 * ks) ^ g) * 8 + 2 * t;
            const int hi = ((2 * ks + 1) ^ g) * 8 + 2 * t;
            uint32_t a[2][4];
#pragma unroll
            for (int mtw = 0; mtw < 2; mtw++) {
                int r0 = (mw * 2 + mtw) * 16 + g;
                a[mtw][0] = *(const uint32_t*)(Ab + r0 * 64 + lo);
                a[mtw][1] = *(const uint32_t*)(Ab + (r0 + 8) * 64 + lo);
                a[mtw][2] = *(const uint32_t*)(Ab + r0 * 64 + hi);
                a[mtw][3] = *(const uint32_t*)(Ab + (r0 + 8) * 64 + hi);
            }
            uint32_t b[NT][2];
#pragma unroll
            for (int ntw = 0; ntw < NT; ntw++) {
                int nr = (nw * NT + ntw) * 8 + g;
                b[ntw][0] = *(const uint32_t*)(Bb + nr * 64 + lo);
                b[ntw][1] = *(const uint32_t*)(Bb + nr * 64 + hi);
            }
#pragma unroll
            for (int mtw = 0; mtw < 2; mtw++)
#pragma unroll
                for (int ntw = 0; ntw < NT; ntw++)
                    mma_f16(d[mtw][ntw], a[mtw], b[ntw]);
        }
        __syncthreads();
    }

    // ---------------- epilogue ----------------
#pragma unroll
    for (int mtw = 0; mtw < 2; mtw++)
#pragma unroll
        for (int ntw = 0; ntw < NT; ntw++)
#pragma unroll
            for (int half = 0; half < 2; half++) {
                int m = m0 + mw * 32 + mtw * 16 + half * 8 + g;
                int n = n0 + nw * (BN / 2) + ntw * 8 + t * 2;
                float v0 = d[mtw][ntw][half * 2 + 0];
                float v1 = d[mtw][ntw][half * 2 + 1];
                if (EPI == 0) {
                    if (z < 2) {          // Q/K fp16 plain (m, 512)
                        __half* dst = Chalf + (size_t)z * 2097152 +
                                      (size_t)m * D_MODEL + n;
                        *(__half2*)dst = __floats2half2_rn(v0, v1);
                    } else {              // V^T fp16 scatter to (b,h,dk,s)
                        int b = m >> 11, s = m & (S_LEN - 1);
                        int h = n >> 6, dd = n & 63;
                        __half* vt = Chalf + 2 * 2097152;
                        size_t base = ((size_t)((b << 3) + h) * DK + dd) * S_LEN + s;
                        vt[base] = __float2half(v0);
                        vt[base + S_LEN] = __float2half(v1);
                    }
                } else if (EPI == 4) {    // fp32 + resid(src perm)
                    size_t o = (size_t)m * ldc + n;
                    const float* rsrc = resid + (size_t)perm_row(m) * D_MODEL + n;
                    float2 rr = *(const float2*)rsrc;
                    *(float2*)(C + o) = make_float2(v0 + rr.x, v1 + rr.y);
                } else if (EPI == 5) {    // fp16 relu(v + bias)
                    size_t o = (size_t)m * ldc + n;
                    float2 bb = *(const float2*)(bias + n);
                    *(__half2*)(Chalf + o) =
                        __floats2half2_rn(fmaxf(v0 + bb.x, 0.f),
                                          fmaxf(v1 + bb.y, 0.f));
                } else {                  // fp32 + bias + resid
                    size_t o = (size_t)m * ldc + n;
                    float2 bb = *(const float2*)(bias + n);
                    float2 rr = *(const float2*)(resid + o);
                    *(float2*)(C + o) = make_float2(v0 + bb.x + rr.x,
                                                    v1 + bb.y + rr.y);
                }
            }
}

// ---------------------------------------------------------------------------
// Scores (fp16 x fp16): S[bh](m,n) = (Q K^T)(m,n) * 0.125 * sph -> fp16
// BM=BN=128, K=64 (single stage), 256 threads, 128B smem rows.
// ---------------------------------------------------------------------------
__global__ void __launch_bounds__(256, 2) scores_f16(
    const __half* __restrict__ qh, const __half* __restrict__ kh,
    const float* __restrict__ sph, __half* __restrict__ s_h) {
    __shared__ __half sAm[128 * 64];
    __shared__ __half sBm[128 * 64];

    const int tid = threadIdx.x;
    const int w = tid >> 5, lane = tid & 31;
    const int g = lane >> 2, t = lane & 3;
    const int mw = w >> 1, nw = w & 1;
    const int m0 = blockIdx.y * 128, n0 = blockIdx.x * 128;
    const int bh = blockIdx.z;

    size_t hoff = (size_t)(bh >> 3) * (S_LEN * D_MODEL) + (size_t)(bh & 7) * DK;
    const __half* Ap = qh + hoff;
    const __half* Bp = kh + hoff;

    const uint32_t sA = smem_to_u32(sAm);
    const uint32_t sB = smem_to_u32(sBm);

#pragma unroll
    for (int i = 0; i < 4; i++) {
        int id = tid + (i << 8);
        int r = id >> 3, c = id & 7;
        uint32_t dst = sA + ((r * 64 + ((c ^ (r & 7)) << 3)) << 1);
        CP_ASYNC16(dst, Ap + (size_t)(m0 + r) * D_MODEL + (c << 3));
    }
#pragma unroll
    for (int i = 0; i < 4; i++) {
        int id = tid + (i << 8);
        int r = id >> 3, c = id & 7;
        uint32_t dst = sB + ((r * 64 + ((c ^ (r & 7)) << 3)) << 1);
        CP_ASYNC16(dst, Bp + (size_t)(n0 + r) * D_MODEL + (c << 3));
    }
    CP_COMMIT();
    CP_WAIT0();
    __syncthreads();

    float d[2][8][4];
#pragma unroll
    for (int i = 0; i < 2; i++)
#pragma unroll
        for (int j = 0; j < 8; j++)
#pragma unroll
            for (int r = 0; r < 4; r++) d[i][j][r] = 0.f;

#pragma unroll
    for (int ks = 0; ks < 4; ks++) {
        const int lo = ((2 * ks) ^ g) * 8 + 2 * t;
        const int hi = ((2 * ks + 1) ^ g) * 8 + 2 * t;
        uint32_t a[2][4];
#pragma unroll
        for (int mtw = 0; mtw < 2; mtw++) {
            int r0 = (mw * 2 + mtw) * 16 + g;
            a[mtw][0] = *(const uint32_t*)(sAm + r0 * 64 + lo);
            a[mtw][1] = *(const uint32_t*)(sAm + (r0 + 8) * 64 + lo);
            a[mtw][2] = *(const uint32_t*)(sAm + r0 * 64 + hi);
            a[mtw][3] = *(const uint32_t*)(sAm + (r0 + 8) * 64 + hi);
        }
        uint32_t b[8][2];
#pragma unroll
        for (int ntw = 0; ntw < 8; ntw++) {
            int nr = nw * 64 + ntw * 8 + g;
            b[ntw][0] = *(const uint32_t*)(sBm + nr * 64 + lo);
            b[ntw][1] = *(const uint32_t*)(sBm + nr * 64 + hi);
        }
#pragma unroll
        for (int mtw = 0; mtw < 2; mtw++)
#pragma unroll
            for (int ntw = 0; ntw < 8; ntw++)
                mma_f16(d[mtw][ntw], a[mtw], b[ntw]);
    }

#pragma unroll
    for (int mtw = 0; mtw < 2; mtw++)
#pragma unroll
        for (int ntw = 0; ntw < 8; ntw++)
#pragma unroll
            for (int half = 0; half < 2; half++) {
                int m = m0 + mw * 32 + mtw * 16 + half * 8 + g;
                int n = n0 + nw * 64 + ntw * 8 + t * 2;
                size_t idx = ((size_t)bh * S_LEN + m) * S_LEN + n;
                float2 sp = *(const float2*)(sph + idx);
                float v0 = d[mtw][ntw][half * 2 + 0] * 0.125f * sp.x;
                float v1 = d[mtw][ntw][half * 2 + 1] * 0.125f * sp.y;
                *(__half2*)(s_h + idx) = __floats2half2_rn(v0, v1);
            }
}

// ---------------------------------------------------------------------------
// Fused softmax + PV. One CTA: 64 q-rows of one (b,h).
// Pass 1: registers -> max/exp/sum -> fp32 p_attn + fp16 p_h.
// Pass 2: O = P @ V^T (fp16 mma, BK=64) -> fp16 gaoh (model layout).
// ---------------------------------------------------------------------------
__global__ void __launch_bounds__(256) softmax_pv(
    const __half* __restrict__ s_h, float* __restrict__ p_out,
    __half* __restrict__ p_h, const __half* __restrict__ vt,
    __half* __restrict__ gaoh) {
    __shared__ __half smA[2][64 * 64];
    __shared__ __half smB[2][64 * 64];

    const int tid = threadIdx.x;
    const int w = tid >> 5, lane = tid & 31;
    const int bh = blockIdx.y;
    const int m0 = blockIdx.x * 64;

    // ---------------- pass 1: softmax ----------------
    {
        const __half* srow0 = s_h + ((size_t)bh * S_LEN + m0) * S_LEN;
        float* prow0 = p_out + ((size_t)bh * S_LEN + m0) * S_LEN;
        __half* phrow0 = p_h + ((size_t)bh * S_LEN + m0) * S_LEN;
        for (int rr = 0; rr < 8; rr++) {
            int r = w * 8 + rr;
            const uint4* srcp = (const uint4*)(srow0 + (size_t)r * S_LEN) + lane;
            float ex[64];
#pragma unroll
            for (int it = 0; it < 8; it++) {
                uint4 v = srcp[it * 32];
                const __half2* hp = (const __half2*)&v;
#pragma unroll
                for (int j = 0; j < 4; j++) {
                    float2 f = __half22float2(hp[j]);
                    ex[it * 8 + 2 * j] = f.x;
                    ex[it * 8 + 2 * j + 1] = f.y;
                }
            }
            float mx = -1e30f;
#pragma unroll
            for (int i = 0; i < 64; i++) mx = fmaxf(mx, ex[i]);
#pragma unroll
            for (int o = 16; o; o >>= 1)
                mx = fmaxf(mx, __shfl_xor_sync(0xffffffffu, mx, o));
            float sum = 0.f;
#pragma unroll
            for (int i = 0; i < 64; i++) {
                ex[i] = __expf(ex[i] - mx);
                sum += ex[i];
            }
#pragma unroll
            for (int o = 16; o; o >>= 1)
                sum += __shfl_xor_sync(0xffffffffu, sum, o);
            float inv = 1.0f / sum;

            float* prow = prow0 + (size_t)r * S_LEN;
            __half* phrow = phrow0 + (size_t)r * S_LEN;
#pragma unroll
            for (int it = 0; it < 8; it++) {
                int base = (it * 32 + lane) * 8;
                float p0 = ex[it * 8 + 0] * inv, p1 = ex[it * 8 + 1] * inv;
                float p2 = ex[it * 8 + 2] * inv, p3 = ex[it * 8 + 3] * inv;
                float p4 = ex[it * 8 + 4] * inv, p5 = ex[it * 8 + 5] * inv;
                float p6 = ex[it * 8 + 6] * inv, p7 = ex[it * 8 + 7] * inv;
                *(float4*)(prow + base) = make_float4(p0, p1, p2, p3);
                *(float4*)(prow + base + 4) = make_float4(p4, p5, p6, p7);
                uint4 pk;
                __half2* pk2 = (__half2*)&pk;
                pk2[0] = __floats2half2_rn(p0, p1);
                pk2[1] = __floats2half2_rn(p2, p3);
                pk2[2] = __floats2half2_rn(p4, p5);
                pk2[3] = __floats2half2_rn(p6, p7);
                *(uint4*)(phrow + base) = pk;
            }
        }
    }
    __threadfence_block();
    __syncthreads();

    // ---------------- pass 2: PV ----------------
    const int g = lane >> 2, t = lane & 3;
    const int mw = w >> 1, nw = w & 1;

    const __half* Ap = p_h + ((size_t)bh * S_LEN + m0) * S_LEN;
    const __half* Bp = vt + (size_t)bh * DK * S_LEN;
    const uint32_t sA = smem_to_u32(smA);
    const uint32_t sB = smem_to_u32(smB);

    float d[4][4];
#pragma unroll
    for (int j = 0; j < 4; j++)
#pragma unroll
        for (int r = 0; r < 4; r++) d[j][r] = 0.f;

    const int NC = S_LEN / 64;

    auto issue = [&](int kc, int stg) {
        int k0 = kc << 6;
#pragma unroll
        for (int i = 0; i < 2; i++) {
            int id = tid + (i << 8);
            int r = id >> 3, c = id & 7;
            uint32_t dst = sA + ((stg * 4096 + r * 64 + ((c ^ (r & 7)) << 3)) << 1);
            CP_ASYNC16(dst, Ap + (size_t)r * S_LEN + k0 + (c << 3));
        }
#pragma unroll
        for (int i = 0; i < 2; i++) {
            int id = tid + (i << 8);
            int r = id >> 3, c = id & 7;
            uint32_t dst = sB + ((stg * 4096 + r * 64 + ((c ^ (r & 7)) << 3)) << 1);
            CP_ASYNC16(dst, Bp + (size_t)r * S_LEN + k0 + (c << 3));
        }
        CP_COMMIT();
    };

    issue(0, 0);
    for (int kc = 0; kc < NC; kc++) {
        if (kc + 1 < NC) {
            issue(kc + 1, (kc + 1) & 1);
            CP_WAIT1();
        } else {
            CP_WAIT0();
        }
        __syncthreads();
        int buf = kc & 1;
        const __half* Ab = smA[buf];
        const __half* Bb = smB[buf];
#pragma unroll
        for (int ks = 0; ks < 4; ks++) {
            const int lo = ((2 * ks) ^ g) * 8 + 2 * t;
            const int hi = ((2 * ks + 1) ^ g) * 8 + 2 * t;
            uint32_t a[4];
            {
                int r0 = mw * 16 + g;
                a[0] = *(const uint32_t*)(Ab + r0 * 64 + lo);
                a[1] = *(const uint32_t*)(Ab + (r0 + 8) * 64 + lo);
                a[2] = *(const uint32_t*)(Ab + r0 * 64 + hi);
                a[3] = *(const uint32_t*)(Ab + (r0 + 8) * 64 + hi);
            }
            uint32_t b[4][2];
#pragma unroll
            for (int ntw = 0; ntw < 4; ntw++) {
                int nr = nw * 32 + ntw * 8 + g;
                b[ntw][0] = *(const uint32_t*)(Bb + nr * 64 + lo);
                b[ntw][1] = *(const uint32_t*)(Bb + nr * 64 + hi);
            }
#pragma unroll
            for (int ntw = 0; ntw < 4; ntw++)
                mma_f16(d[ntw], a, b[ntw]);
        }
        __syncthreads();
    }

    int b = bh >> 3, h = bh & 7;
#pragma unroll
    for (int ntw = 0; ntw < 4; ntw++)
#pragma unroll
        for (int half = 0; half < 2; half++) {
            int m = m0 + mw * 16 + half * 8 + g;
            int n = nw * 32 + ntw * 8 + t * 2;
            size_t dst = ((size_t)(b * S_LEN + m)) * D_MODEL + h * DK + n;
            *(__half2*)(gaoh + dst) =
                __floats2half2_rn(d[ntw][half * 2 + 0], d[ntw][half * 2 + 1]);
        }
}

// ---------------------------------------------------------------------------
// LayerNorm kernels
// ---------------------------------------------------------------------------
__device__ __forceinline__ float blockSum256(float v, float* sred) {
#pragma unroll
    for (int o = 16; o; o >>= 1) v += __shfl_xor_sync(0xffffffffu, v, o);
    __syncthreads();
    if ((threadIdx.x & 31) == 0) sred[threadIdx.x >> 5] = v;
    __syncthreads();
    float s = sred[0];
#pragma unroll
    for (int i = 1; i < 8; i++) s += sred[i];
    return s;
}

__global__ void __launch_bounds__(256) ln_double_kernel(
    const float* __restrict__ tin, const float* __restrict__ src,
    const float* __restrict__ ga, const float* __restrict__ ba,
    const float* __restrict__ g1w, const float* __restrict__ b1w,
    float* __restrict__ hout, __half* __restrict__ hh) {
    __shared__ float sred[8];
    int m = blockIdx.x, t = threadIdx.x;
    float2 v = ((const float2*)(tin + (size_t)m * D_MODEL))[t];
    float2 xv = ((const float2*)(src + (size_t)perm_row(m) * D_MODEL))[t];
    float mu = blockSum256(v.x + v.y, sred) * (1.f / 512.f);
    float dx = v.x - mu, dy = v.y - mu;
    float var = blockSum256(dx * dx + dy * dy, sred) * (1.f / 512.f);
    float rs = rsqrtf(var + 1e-6f);
    int d0 = t * 2;
    float u0 = xv.x + dx * rs * ga[d0] + ba[d0];
    float u1 = xv.y + dy * rs * ga[d0 + 1] + ba[d0 + 1];
    mu = blockSum256(u0 + u1, sred) * (1.f / 512.f);
    dx = u0 - mu; dy = u1 - mu;
    var = blockSum256(dx * dx + dy * dy, sred) * (1.f / 512.f);
    rs = rsqrtf(var + 1e-5f);
    float h0 = dx * rs * g1w[d0] + b1w[d0];
    float h1 = dy * rs * g1w[d0 + 1] + b1w[d0 + 1];
    ((float2*)(hout + (size_t)m * D_MODEL))[t] = make_float2(h0, h1);
    ((__half2*)(hh + (size_t)m * D_MODEL))[t] = __floats2half2_rn(h0, h1);
}

__global__ void __launch_bounds__(256) ln_final_kernel(
    const float* __restrict__ tin, const float* __restrict__ g2w,
    const float* __restrict__ b2w, float* __restrict__ out) {
    __shared__ float sred[8];
    int m = blockIdx.x, t = threadIdx.x;
    float2 v = ((const float2*)(tin + (size_t)m * D_MODEL))[t];
    float mu = blockSum256(v.x + v.y, sred) * (1.f / 512.f);
    float dx = v.x - mu, dy = v.y - mu;
    float var = blockSum256(dx * dx + dy * dy, sred) * (1.f / 512.f);
    float rs = rsqrtf(var + 1e-5f);
    int d0 = t * 2;
    int b = m >> 11;
    int s = m & (S_LEN - 1);
    float2 ov = make_float2(dx * rs * g2w[d0] + b2w[d0],
                            dy * rs * g2w[d0 + 1] + b2w[d0 + 1]);
    ((float2*)(out + ((size_t)(s * B_SZ + b)) * D_MODEL))[t] = ov;
}

// ---------------------------------------------------------------------------
// Launch
// ---------------------------------------------------------------------------
#define HSMEM_BN128 (STAGES * (128 + 128) * 64 * 2)   // 98304
#define HSMEM_BN64  (STAGES * (128 + 64) * 64 * 2)    // 73728

extern "C" void kernel_launch(void* const* d_in, const int* in_sizes, int n_in,
                              void* d_out, int out_size) {
    const float* src    = (const float*)d_in[0];
    const float* sph    = (const float*)d_in[1];
    const float* w_qs   = (const float*)d_in[2];
    const float* w_ks   = (const float*)d_in[3];
    const float* w_vs   = (const float*)d_in[4];
    const float* w_fc   = (const float*)d_in[5];
    const float* g_attn = (const float*)d_in[6];
    const float* b_attn = (const float*)d_in[7];
    const float* w1     = (const float*)d_in[8];
    const float* b1     = (const float*)d_in[9];
    const float* w2     = (const float*)d_in[10];
    const float* b2     = (const float*)d_in[11];
    const float* g1w    = (const float*)d_in[12];
    const float* bn1    = (const float*)d_in[13];
    const float* g2w    = (const float*)d_in[14];
    const float* bn2    = (const float*)d_in[15];

    float* out = (float*)d_out;
    float* p_out = out + OUT_ELEMS;

    void* sp = nullptr;
    cudaGetSymbolAddress(&sp, g_scratch);
    float* scr = (float*)sp;
    float* gt1 = scr + OFF_T1;
    float* gh  = scr + OFF_H;
    __half* xh   = (__half*)(scr + OFF_XH);
    __half* qh   = (__half*)(scr + OFF_QH);
    __half* kh   = (__half*)(scr + OFF_KH);
    __half* vt_h = (__half*)(scr + OFF_VTH);
    __half* gaoh = (__half*)(scr + OFF_GAOH);
    __half* hh   = (__half*)(scr + OFF_HH);
    __half* ffh  = (__half*)(scr + OFF_FFH);
    __half* wqh  = (__half*)(scr + OFF_WQH);
    __half* wkh  = (__half*)(scr + OFF_WKH);
    __half* wvh  = (__half*)(scr + OFF_WVH);
    __half* wfch = (__half*)(scr + OFF_WFCH);
    __half* w1h  = (__half*)(scr + OFF_W1H);
    __half* w2h  = (__half*)(scr + OFF_W2H);
    __half* s_h  = (__half*)(scr + OFF_SH);
    __half* p_h  = (__half*)(scr + OFF_PH);

    cudaFuncSetAttribute(gemm_h<0, 128>,
                         cudaFuncAttributeMaxDynamicSharedMemorySize, HSMEM_BN128);
    cudaFuncSetAttribute(gemm_h<4, 64>,
                         cudaFuncAttributeMaxDynamicSharedMemorySize, HSMEM_BN64);
    cudaFuncSetAttribute(gemm_h<5, 128>,
                         cudaFuncAttributeMaxDynamicSharedMemorySize, HSMEM_BN128);
    cudaFuncSetAttribute(gemm_h<6, 64>,
                         cudaFuncAttributeMaxDynamicSharedMemorySize, HSMEM_BN64);

    // 0. fp16 conversions (src perm + all weights)
    convert_all<<<5120, 256>>>(src, w_qs, w_ks, w_vs, w_fc, w1, w2,
                               xh, wqh, wkh, wvh, wfch, w1h, w2h);

    // 1. fused QKV (fp16): z=0 Q, z=1 K, z=2 V^T
    dim3 gqkv(D_MODEL / 128, M_ROWS / 128, 3);
    gemm_h<0, 128><<<gqkv, 256, HSMEM_BN128>>>(
        xh, D_MODEL, wqh, wkh, wvh, D_MODEL, D_MODEL,
        nullptr, nullptr, nullptr, 0, qh);

    // 2. scores = (Q K^T) * 0.125 * sph -> fp16
    dim3 gsc(S_LEN / 128, S_LEN / 128, B_SZ * H_HEADS);
    scores_f16<<<gsc, 256>>>(qh, kh, sph, s_h);

    // 3. fused softmax + PV -> p_out (fp32) and gaoh (fp16)
    softmax_pv<<<dim3(S_LEN / 64, B_SZ * H_HEADS), 256>>>(s_h, p_out, p_h,
                                                          vt_h, gaoh);

    // 4. fc projection + residual(src perm) -> gt1 fp32
    dim3 gfc(D_MODEL / 64, M_ROWS / 128, 1);
    gemm_h<4, 64><<<gfc, 256, HSMEM_BN64>>>(
        gaoh, D_MODEL, wfch, nullptr, nullptr, D_MODEL, D_MODEL,
        gt1, nullptr, src, D_MODEL, nullptr);

    // 5. double LayerNorm -> h fp32 + hh fp16
    ln_double_kernel<<<M_ROWS, 256>>>(gt1, src, g_attn, b_attn, g1w, bn1,
                                      gh, hh);

    // 6. FFN up: relu(h @ w1^T + b1) -> ffh fp16
    dim3 gffn(F_FFN / 128, M_ROWS / 128, 1);
    gemm_h<5, 128><<<gffn, 256, HSMEM_BN128>>>(
        hh, D_MODEL, w1h, nullptr, nullptr, D_MODEL, D_MODEL,
        nullptr, b1, nullptr, F_FFN, ffh);

    // 7. FFN down + b2 + residual(h) -> gt1 fp32
    gemm_h<6, 64><<<gfc, 256, HSMEM_BN64>>>(
        ffh, F_FFN, w2h, nullptr, nullptr, F_FFN, F_FFN,
        gt1, b2, gh, D_MODEL, nullptr);

    // 8. final LN + transposed store
    ln_final_kernel<<<M_ROWS, 256>>>(gt1, g2w, bn2, out);
}

// round 9
// speedup vs baseline: 8.7921x; 1.0584x over previous
#include <cuda_runtime.h>
#include <cuda_fp16.h>
#include <cstdint>
#include <cstddef>

// ---------------------------------------------------------------------------
// Problem constants
// ---------------------------------------------------------------------------
#define S_LEN 2048
#define B_SZ  2
#define D_MODEL 512
#define H_HEADS 8
#define DK 64
#define F_FFN 2048
#define M_ROWS (B_SZ * S_LEN)              // 4096
#define OUT_ELEMS (S_LEN * B_SZ * D_MODEL) // 2097152

// Scratch layout (float offsets)
#define OFF_T1   0                         // 2M floats
#define OFF_H    2097152                   // 2M floats
#define OFF_XH   4194304                   // 2M halves = 1M floats
#define OFF_QH   5242880                   // Q,K,VT each 2M halves = 1M floats
#define OFF_KH   6291456
#define OFF_VTH  7340032
#define OFF_GAOH 8388608                   // 1M floats
#define OFF_HH   9437184                   // 1M floats
#define OFF_FFH  10485760                  // 8M halves = 4M floats
#define OFF_WQH  14680064                  // 128K floats each
#define OFF_WKH  14811136
#define OFF_WVH  14942208
#define OFF_WFCH 15073280
#define OFF_W1H  15204352                  // 512K floats
#define OFF_W2H  15728640                  // 512K floats
#define OFF_SH   16252928                  // 67108864 halves = 33554432 floats
#define OFF_PART 49807360                  // 32768*32 float2 = 2097152 floats
#define SCRATCH_FLOATS 51904512

__device__ float g_scratch[SCRATCH_FLOATS];

// ---------------------------------------------------------------------------
// PTX helpers
// ---------------------------------------------------------------------------
__device__ __forceinline__ uint32_t smem_to_u32(const void* p) {
    uint32_t a;
    asm("{ .reg .u64 t; cvta.to.shared.u64 t, %1; cvt.u32.u64 %0, t; }"
        : "=r"(a) : "l"(p));
    return a;
}

#define CP_ASYNC16(dst, src) \
    asm volatile("cp.async.cg.shared.global [%0], [%1], 16;\n" \
                 :: "r"(dst), "l"(src))
#define CP_COMMIT() asm volatile("cp.async.commit_group;\n" ::: "memory")
#define CP_WAIT1()  asm volatile("cp.async.wait_group 1;\n" ::: "memory")
#define CP_WAIT0()  asm volatile("cp.async.wait_group 0;\n" ::: "memory")

__device__ __forceinline__ void mma_f16(float (&dd)[4], const uint32_t (&a)[4],
                                        const uint32_t (&b)[2]) {
    asm volatile(
        "mma.sync.aligned.m16n8k16.row.col.f32.f16.f16.f32 "
        "{%0,%1,%2,%3}, {%4,%5,%6,%7}, {%8,%9}, {%0,%1,%2,%3};\n"
        : "+f"(dd[0]), "+f"(dd[1]), "+f"(dd[2]), "+f"(dd[3])
        : "r"(a[0]), "r"(a[1]), "r"(a[2]), "r"(a[3]), "r"(b[0]), "r"(b[1]));
}

// permuted src row: x[m] = src[(s*B + b)] with m = b*S + s
__device__ __forceinline__ int perm_row(int m) {
    return ((m & (S_LEN - 1)) << 1) + (m >> 11);
}

// ---------------------------------------------------------------------------
// Conversion prep: src (permuted) + 6 weight matrices -> fp16
// ---------------------------------------------------------------------------
__global__ void __launch_bounds__(256) convert_all(
    const float* __restrict__ src,
    const float* __restrict__ wq, const float* __restrict__ wk,
    const float* __restrict__ wv, const float* __restrict__ wfc,
    const float* __restrict__ w1, const float* __restrict__ w2,
    __half* __restrict__ xh, __half* __restrict__ wqh, __half* __restrict__ wkh,
    __half* __restrict__ wvh, __half* __restrict__ wfch,
    __half* __restrict__ w1h, __half* __restrict__ w2h) {
    int i4 = blockIdx.x * 256 + threadIdx.x;   // float4 index
    if (i4 < 524288) {                          // xh with row permutation
        int m = i4 >> 7;
        int c = (i4 & 127) << 2;
        float4 v = *(const float4*)(src + (size_t)perm_row(m) * D_MODEL + c);
        __half2* d = (__half2*)(xh + (size_t)m * D_MODEL + c);
        d[0] = __floats2half2_rn(v.x, v.y);
        d[1] = __floats2half2_rn(v.z, v.w);
        return;
    }
    i4 -= 524288;
    const float* sp;
    __half* dp;
    if (i4 < 65536) { sp = wq; dp = wqh; }
    else if (i4 < 131072) { sp = wk; dp = wkh; i4 -= 65536; }
    else if (i4 < 196608) { sp = wv; dp = wvh; i4 -= 131072; }
    else if (i4 < 262144) { sp = wfc; dp = wfch; i4 -= 196608; }
    else if (i4 < 524288) { sp = w1; dp = w1h; i4 -= 262144; }
    else { sp = w2; dp = w2h; i4 -= 524288; }
    float4 v = *(const float4*)(sp + (size_t)i4 * 4);
    __half2* d = (__half2*)(dp + (size_t)i4 * 4);
    d[0] = __floats2half2_rn(v.x, v.y);
    d[1] = __floats2half2_rn(v.z, v.w);
}

// ---------------------------------------------------------------------------
// fp16 mma.sync GEMM: C[m,n] = sum_k A[m,k] * Bw[n,k]  (K-major halves)
// BM=128, BN template, BK=64, 3-stage cp.async ring, 256 threads (4m x 2n),
// 128-byte smem rows with conflict-free 8-chunk XOR swizzle.
//
// EPI: 0 = fused QKV (z selects B: B0/B1/B2; z<2 plain fp16, z=2 V^T scatter)
//      4 = fp32 out + resid(src perm)
//      5 = fp16 out relu(v + bias)
//      6 = fp32 out + bias + resid(fp32)
// ---------------------------------------------------------------------------
#define STAGES 3

template <int EPI, int BN>
__global__ void __launch_bounds__(256, 2) gemm_h(
    const __half* __restrict__ A, int lda,
    const __half* __restrict__ B0, const __half* __restrict__ B1,
    const __half* __restrict__ B2, int ldb,
    int K, float* __restrict__ C,
    const float* __restrict__ bias, const float* __restrict__ resid,
    int ldc, __half* __restrict__ Chalf) {
    constexpr int NT = BN / 16;
    constexpr int ASTG = 128 * 64;           // halves per A stage
    constexpr int BSTG = BN * 64;
    extern __shared__ __half hsm[];
    __half* smA = hsm;
    __half* smB = hsm + STAGES * ASTG;

    const int tid = threadIdx.x;
    const int w = tid >> 5, lane = tid & 31;
    const int g = lane >> 2, t = lane & 3;
    const int mw = w >> 1, nw = w & 1;
    const int m0 = blockIdx.y * 128, n0 = blockIdx.x * BN;
    const int z = blockIdx.z;

    const __half* Bp = (EPI == 0) ? ((z == 0) ? B0 : (z == 1) ? B1 : B2) : B0;

    const uint32_t sA = smem_to_u32(smA);
    const uint32_t sB = smem_to_u32(smB);

    float d[2][NT][4];
#pragma unroll
    for (int i = 0; i < 2; i++)
#pragma unroll
        for (int j = 0; j < NT; j++)
#pragma unroll
            for (int r = 0; r < 4; r++) d[i][j][r] = 0.f;

    const int NC = K >> 6;

    auto issue = [&](int kc, int stg) {
        int k0 = kc << 6;
#pragma unroll
        for (int i = 0; i < 4; i++) {
            int id = tid + (i << 8);          // 128 rows x 8 chunks
            int r = id >> 3, c = id & 7;
            uint32_t dst = sA + ((stg * ASTG + r * 64 + ((c ^ (r & 7)) << 3)) << 1);
            CP_ASYNC16(dst, A + (size_t)(m0 + r) * lda + k0 + (c << 3));
        }
#pragma unroll
        for (int i = 0; i < BN / 32; i++) {
            int id = tid + (i << 8);
            int r = id >> 3, c = id & 7;
            uint32_t dst = sB + ((stg * BSTG + r * 64 + ((c ^ (r & 7)) << 3)) << 1);
            CP_ASYNC16(dst, Bp + (size_t)(n0 + r) * ldb + k0 + (c << 3));
        }
        CP_COMMIT();
    };

    issue(0, 0);
    if (NC > 1) issue(1, 1);

    for (int kc = 0; kc < NC; kc++) {
        if (kc == NC - 1) { CP_WAIT0(); } else { CP_WAIT1(); }
        __syncthreads();
        if (kc + 2 < NC) issue(kc + 2, (kc + 2) % STAGES);

        int buf = kc % STAGES;
        const __half* Ab = smA + buf * ASTG;
        const __half* Bb = smB + buf * BSTG;
#pragma unroll
        for (int ks = 0; ks < 4; ks++) {
            const int lo = ((2 * ks) ^ g) * 8 + 2 * t;
            const int hi = ((2 * ks + 1) ^ g) * 8 + 2 * t;
            uint32_t a[2][4];
#pragma unroll
            for (int mtw = 0; mtw < 2; mtw++) {
                int r0 = (mw * 2 + mtw) * 16 + g;
                a[mtw][0] = *(const uint32_t*)(Ab + r0 * 64 + lo);
                a[mtw][1] = *(const uint32_t*)(Ab + (r0 + 8) * 64 + lo);
                a[mtw][2] = *(const uint32_t*)(Ab + r0 * 64 + hi);
                a[mtw][3] = *(const uint32_t*)(Ab + (r0 + 8) * 64 + hi);
            }
            uint32_t b[NT][2];
#pragma unroll
            for (int ntw = 0; ntw < NT; ntw++) {
                int nr = (nw * NT + ntw) * 8 + g;
                b[ntw][0] = *(const uint32_t*)(Bb + nr * 64 + lo);
                b[ntw][1] = *(const uint32_t*)(Bb + nr * 64 + hi);
            }
#pragma unroll
            for (int mtw = 0; mtw < 2; mtw++)
#pragma unroll
                for (int ntw = 0; ntw < NT; ntw++)
                    mma_f16(d[mtw][ntw], a[mtw], b[ntw]);
        }
        __syncthreads();
    }

    // ---------------- epilogue ----------------
#pragma unroll
    for (int mtw = 0; mtw < 2; mtw++)
#pragma unroll
        for (int ntw = 0; ntw < NT; ntw++)
#pragma unroll
            for (int half = 0; half < 2; half++) {
                int m = m0 + mw * 32 + mtw * 16 + half * 8 + g;
                int n = n0 + nw * (BN / 2) + ntw * 8 + t * 2;
                float v0 = d[mtw][ntw][half * 2 + 0];
                float v1 = d[mtw][ntw][half * 2 + 1];
                if (EPI == 0) {
                    if (z < 2) {          // Q/K fp16 plain (m, 512)
                        __half* dst = Chalf + (size_t)z * 2097152 +
                                      (size_t)m * D_MODEL + n;
                        *(__half2*)dst = __floats2half2_rn(v0, v1);
                    } else {              // V^T fp16 scatter to (b,h,dk,s)
                        int b = m >> 11, s = m & (S_LEN - 1);
                        int h = n >> 6, dd = n & 63;
                        __half* vt = Chalf + 2 * 2097152;
                        size_t base = ((size_t)((b << 3) + h) * DK + dd) * S_LEN + s;
                        vt[base] = __float2half(v0);
                        vt[base + S_LEN] = __float2half(v1);
                    }
                } else if (EPI == 4) {    // fp32 + resid(src perm)
                    size_t o = (size_t)m * ldc + n;
                    const float* rsrc = resid + (size_t)perm_row(m) * D_MODEL + n;
                    float2 rr = *(const float2*)rsrc;
                    *(float2*)(C + o) = make_float2(v0 + rr.x, v1 + rr.y);
                } else if (EPI == 5) {    // fp16 relu(v + bias)
                    size_t o = (size_t)m * ldc + n;
                    float2 bb = *(const float2*)(bias + n);
                    *(__half2*)(Chalf + o) =
                        __floats2half2_rn(fmaxf(v0 + bb.x, 0.f),
                                          fmaxf(v1 + bb.y, 0.f));
                } else {                  // fp32 + bias + resid
                    size_t o = (size_t)m * ldc + n;
                    float2 bb = *(const float2*)(bias + n);
                    float2 rr = *(const float2*)(resid + o);
                    *(float2*)(C + o) = make_float2(v0 + bb.x + rr.x,
                                                    v1 + bb.y + rr.y);
                }
            }
}

// ---------------------------------------------------------------------------
// Scores (fp16 x fp16): S[bh](m,n) = (Q K^T)(m,n) * 0.125 * sph -> fp16
// + per-(row, 64-col-tile) softmax partials (max, sum-exp) for split softmax.
// BM=BN=128, K=64 (single stage), 256 threads, 128B smem rows.
// ---------------------------------------------------------------------------
__global__ void __launch_bounds__(256, 2) scores_f16(
    const __half* __restrict__ qh, const __half* __restrict__ kh,
    const float* __restrict__ sph, __half* __restrict__ s_h,
    float2* __restrict__ part) {
    __shared__ __half sAm[128 * 64];
    __shared__ __half sBm[128 * 64];

    const int tid = threadIdx.x;
    const int w = tid >> 5, lane = tid & 31;
    const int g = lane >> 2, t = lane & 3;
    const int mw = w >> 1, nw = w & 1;
    const int m0 = blockIdx.y * 128, n0 = blockIdx.x * 128;
    const int bh = blockIdx.z;

    size_t hoff = (size_t)(bh >> 3) * (S_LEN * D_MODEL) + (size_t)(bh & 7) * DK;
    const __half* Ap = qh + hoff;
    const __half* Bp = kh + hoff;

    const uint32_t sA = smem_to_u32(sAm);
    const uint32_t sB = smem_to_u32(sBm);

#pragma unroll
    for (int i = 0; i < 4; i++) {
        int id = tid + (i << 8);
        int r = id >> 3, c = id & 7;
        uint32_t dst = sA + ((r * 64 + ((c ^ (r & 7)) << 3)) << 1);
        CP_ASYNC16(dst, Ap + (size_t)(m0 + r) * D_MODEL + (c << 3));
    }
#pragma unroll
    for (int i = 0; i < 4; i++) {
        int id = tid + (i << 8);
        int r = id >> 3, c = id & 7;
        uint32_t dst = sB + ((r * 64 + ((c ^ (r & 7)) << 3)) << 1);
        CP_ASYNC16(dst, Bp + (size_t)(n0 + r) * D_MODEL + (c << 3));
    }
    CP_COMMIT();
    CP_WAIT0();
    __syncthreads();

    float d[2][8][4];
#pragma unroll
    for (int i = 0; i < 2; i++)
#pragma unroll
        for (int j = 0; j < 8; j++)
#pragma unroll
            for (int r = 0; r < 4; r++) d[i][j][r] = 0.f;

#pragma unroll
    for (int ks = 0; ks < 4; ks++) {
        const int lo = ((2 * ks) ^ g) * 8 + 2 * t;
        const int hi = ((2 * ks + 1) ^ g) * 8 + 2 * t;
        uint32_t a[2][4];
#pragma unroll
        for (int mtw = 0; mtw < 2; mtw++) {
            int r0 = (mw * 2 + mtw) * 16 + g;
            a[mtw][0] = *(const uint32_t*)(sAm + r0 * 64 + lo);
            a[mtw][1] = *(const uint32_t*)(sAm + (r0 + 8) * 64 + lo);
            a[mtw][2] = *(const uint32_t*)(sAm + r0 * 64 + hi);
            a[mtw][3] = *(const uint32_t*)(sAm + (r0 + 8) * 64 + hi);
        }
        uint32_t b[8][2];
#pragma unroll
        for (int ntw = 0; ntw < 8; ntw++) {
            int nr = nw * 64 + ntw * 8 + g;
            b[ntw][0] = *(const uint32_t*)(sBm + nr * 64 + lo);
            b[ntw][1] = *(const uint32_t*)(sBm + nr * 64 + hi);
        }
#pragma unroll
        for (int mtw = 0; mtw < 2; mtw++)
#pragma unroll
            for (int ntw = 0; ntw < 8; ntw++)
                mma_f16(d[mtw][ntw], a[mtw], b[ntw]);
    }

    // epilogue: per row (mtw, half) -> store fp16 scores + tile partials
#pragma unroll
    for (int mtw = 0; mtw < 2; mtw++)
#pragma unroll
        for (int half = 0; half < 2; half++) {
            int m = m0 + mw * 32 + mtw * 16 + half * 8 + g;
            float tmp[16];
#pragma unroll
            for (int ntw = 0; ntw < 8; ntw++) {
                int n = n0 + nw * 64 + ntw * 8 + t * 2;
                size_t idx = ((size_t)bh * S_LEN + m) * S_LEN + n;
                float2 sp = *(const float2*)(sph + idx);
                float v0 = d[mtw][ntw][half * 2 + 0] * 0.125f * sp.x;
                float v1 = d[mtw][ntw][half * 2 + 1] * 0.125f * sp.y;
                __half2 h2 = __floats2half2_rn(v0, v1);
                *(__half2*)(s_h + idx) = h2;
                // partials from the fp16-rounded values (bit-consistent with
                // the exp inputs in softmax_pv phase 2)
                float2 fr = __half22float2(h2);
                tmp[ntw * 2] = fr.x;
                tmp[ntw * 2 + 1] = fr.y;
            }
            float mx = tmp[0];
#pragma unroll
            for (int i = 1; i < 16; i++) mx = fmaxf(mx, tmp[i]);
            mx = fmaxf(mx, __shfl_xor_sync(0xffffffffu, mx, 1));
            mx = fmaxf(mx, __shfl_xor_sync(0xffffffffu, mx, 2));
            float se = 0.f;
#pragma unroll
            for (int i = 0; i < 16; i++) se += __expf(tmp[i] - mx);
            se += __shfl_xor_sync(0xffffffffu, se, 1);
            se += __shfl_xor_sync(0xffffffffu, se, 2);
            if (t == 0) {
                int tile = blockIdx.x * 2 + nw;   // 32 tiles of 64 cols
                part[((size_t)bh * S_LEN + m) * 32 + tile] =
                    make_float2(mx, se);
            }
        }
}

// ---------------------------------------------------------------------------
// Fused softmax + PV without the p_h round-trip.
// One CTA: 64 q-rows of one (b,h).
// Phase 0: combine 32 partials/row -> (M, 1/S) in smem.
// Phase 2: per 64-key chunk: stage raw s_h + V; normalize chunk in place in
//          smem (p = exp(s-M)/S), write fp32 p_attn from the chunk, then PV
//          MMA on the normalized tile. Output fp16 gaoh (model layout).
// ---------------------------------------------------------------------------
__global__ void __launch_bounds__(256) softmax_pv(
    const __half* __restrict__ s_h, const float2* __restrict__ part,
    const __half* __restrict__ vt, float* __restrict__ p_out,
    __half* __restrict__ gaoh) {
    __shared__ __half smA[2][64 * 64];
    __shared__ __half smB[2][64 * 64];
    __shared__ float rowM[64];
    __shared__ float rowInv[64];

    const int tid = threadIdx.x;
    const int w = tid >> 5, lane = tid & 31;
    const int bh = blockIdx.y;
    const int m0 = blockIdx.x * 64;

    // ---------------- phase 0: global (M, 1/S) per row ----------------
    {
        const float2* pbase = part + ((size_t)bh * S_LEN + m0) * 32;
#pragma unroll
        for (int rr = 0; rr < 8; rr++) {
            int r = w * 8 + rr;
            float2 pm = pbase[(size_t)r * 32 + lane];   // lane = tile 0..31
            float M = pm.x;
#pragma unroll
            for (int o = 16; o; o >>= 1)
                M = fmaxf(M, __shfl_xor_sync(0xffffffffu, M, o));
            float contrib = pm.y * __expf(pm.x - M);
#pragma unroll
            for (int o = 16; o; o >>= 1)
                contrib += __shfl_xor_sync(0xffffffffu, contrib, o);
            if (lane == 0) {
                rowM[r] = M;
                rowInv[r] = 1.0f / contrib;
            }
        }
    }
    __syncthreads();

    // ---------------- phase 2: normalize + p_out + PV ----------------
    const int g = lane >> 2, t = lane & 3;
    const int mw = w >> 1, nw = w & 1;

    const __half* Ap = s_h + ((size_t)bh * S_LEN + m0) * S_LEN;
    float* Pp = p_out + ((size_t)bh * S_LEN + m0) * S_LEN;
    const __half* Bp = vt + (size_t)bh * DK * S_LEN;
    const uint32_t sA = smem_to_u32(smA);
    const uint32_t sB = smem_to_u32(smB);

    float d[4][4];
#pragma unroll
    for (int j = 0; j < 4; j++)
#pragma unroll
        for (int r = 0; r < 4; r++) d[j][r] = 0.f;

    const int NC = S_LEN / 64;   // 32

    auto issue = [&](int kc, int stg) {
        int k0 = kc << 6;
#pragma unroll
        for (int i = 0; i < 2; i++) {
            int id = tid + (i << 8);
            int r = id >> 3, c = id & 7;
            uint32_t dst = sA + ((stg * 4096 + r * 64 + ((c ^ (r & 7)) << 3)) << 1);
            CP_ASYNC16(dst, Ap + (size_t)r * S_LEN + k0 + (c << 3));
        }
#pragma unroll
        for (int i = 0; i < 2; i++) {
            int id = tid + (i << 8);
            int r = id >> 3, c = id & 7;
            uint32_t dst = sB + ((stg * 4096 + r * 64 + ((c ^ (r & 7)) << 3)) << 1);
            CP_ASYNC16(dst, Bp + (size_t)r * S_LEN + k0 + (c << 3));
        }
        CP_COMMIT();
    };

    issue(0, 0);
    for (int kc = 0; kc < NC; kc++) {
        int k0 = kc << 6;
        if (kc + 1 < NC) {
            issue(kc + 1, (kc + 1) & 1);
            CP_WAIT1();
        } else {
            CP_WAIT0();
        }
        __syncthreads();
        int buf = kc & 1;
        __half* Ab = smA[buf];
        const __half* Bb = smB[buf];

        // normalize chunk in place + write fp32 p_attn
#pragma unroll
        for (int i = 0; i < 2; i++) {
            int id = tid + (i << 8);
            int r = id >> 3, c = id & 7;
            __half* sp = Ab + r * 64 + ((c ^ (r & 7)) << 3);
            uint4 raw = *(const uint4*)sp;
            const __half2* h2 = (const __half2*)&raw;
            float M = rowM[r], inv = rowInv[r];
            float p[8];
#pragma unroll
            for (int j = 0; j < 4; j++) {
                float2 f = __half22float2(h2[j]);
                p[2 * j] = __expf(f.x - M) * inv;
                p[2 * j + 1] = __expf(f.y - M) * inv;
            }
            float* pd = Pp + (size_t)r * S_LEN + k0 + (c << 3);
            *(float4*)pd = make_float4(p[0], p[1], p[2], p[3]);
            *(float4*)(pd + 4) = make_float4(p[4], p[5], p[6], p[7]);
            uint4 pk;
            __half2* pk2 = (__half2*)&pk;
#pragma unroll
            for (int j = 0; j < 4; j++)
                pk2[j] = __floats2half2_rn(p[2 * j], p[2 * j + 1]);
            *(uint4*)sp = pk;
        }
        __syncthreads();

        // PV MMA on normalized tile
#pragma unroll
        for (int ks = 0; ks < 4; ks++) {
            const int lo = ((2 * ks) ^ g) * 8 + 2 * t;
            const int hi = ((2 * ks + 1) ^ g) * 8 + 2 * t;
            uint32_t a[4];
            {
                int r0 = mw * 16 + g;
                a[0] = *(const uint32_t*)(Ab + r0 * 64 + lo);
                a[1] = *(const uint32_t*)(Ab + (r0 + 8) * 64 + lo);
                a[2] = *(const uint32_t*)(Ab + r0 * 64 + hi);
                a[3] = *(const uint32_t*)(Ab + (r0 + 8) * 64 + hi);
            }
            uint32_t b[4][2];
#pragma unroll
            for (int ntw = 0; ntw < 4; ntw++) {
                int nr = nw * 32 + ntw * 8 + g;
                b[ntw][0] = *(const uint32_t*)(Bb + nr * 64 + lo);
                b[ntw][1] = *(const uint32_t*)(Bb + nr * 64 + hi);
            }
#pragma unroll
            for (int ntw = 0; ntw < 4; ntw++)
                mma_f16(d[ntw], a, b[ntw]);
        }
        __syncthreads();
    }

    int b = bh >> 3, h = bh & 7;
#pragma unroll
    for (int ntw = 0; ntw < 4; ntw++)
#pragma unroll
        for (int half = 0; half < 2; half++) {
            int m = m0 + mw * 16 + half * 8 + g;
            int n = nw * 32 + ntw * 8 + t * 2;
            size_t dst = ((size_t)(b * S_LEN + m)) * D_MODEL + h * DK + n;
            *(__half2*)(gaoh + dst) =
                __floats2half2_rn(d[ntw][half * 2 + 0], d[ntw][half * 2 + 1]);
        }
}

// ---------------------------------------------------------------------------
// LayerNorm kernels
// ---------------------------------------------------------------------------
__device__ __forceinline__ float blockSum256(float v, float* sred) {
#pragma unroll
    for (int o = 16; o; o >>= 1) v += __shfl_xor_sync(0xffffffffu, v, o);
    __syncthreads();
    if ((threadIdx.x & 31) == 0) sred[threadIdx.x >> 5] = v;
    __syncthreads();
    float s = sred[0];
#pragma unroll
    for (int i = 1; i < 8; i++) s += sred[i];
    return s;
}

__global__ void __launch_bounds__(256) ln_double_kernel(
    const float* __restrict__ tin, const float* __restrict__ src,
    const float* __restrict__ ga, const float* __restrict__ ba,
    const float* __restrict__ g1w, const float* __restrict__ b1w,
    float* __restrict__ hout, __half* __restrict__ hh) {
    __shared__ float sred[8];
    int m = blockIdx.x, t = threadIdx.x;
    float2 v = ((const float2*)(tin + (size_t)m * D_MODEL))[t];
    float2 xv = ((const float2*)(src + (size_t)perm_row(m) * D_MODEL))[t];
    float mu = blockSum256(v.x + v.y, sred) * (1.f / 512.f);
    float dx = v.x - mu, dy = v.y - mu;
    float var = blockSum256(dx * dx + dy * dy, sred) * (1.f / 512.f);
    float rs = rsqrtf(var + 1e-6f);
    int d0 = t * 2;
    float u0 = xv.x + dx * rs * ga[d0] + ba[d0];
    float u1 = xv.y + dy * rs * ga[d0 + 1] + ba[d0 + 1];
    mu = blockSum256(u0 + u1, sred) * (1.f / 512.f);
    dx = u0 - mu; dy = u1 - mu;
    var = blockSum256(dx * dx + dy * dy, sred) * (1.f / 512.f);
    rs = rsqrtf(var + 1e-5f);
    float h0 = dx * rs * g1w[d0] + b1w[d0];
    float h1 = dy * rs * g1w[d0 + 1] + b1w[d0 + 1];
    ((float2*)(hout + (size_t)m * D_MODEL))[t] = make_float2(h0, h1);
    ((__half2*)(hh + (size_t)m * D_MODEL))[t] = __floats2half2_rn(h0, h1);
}

__global__ void __launch_bounds__(256) ln_final_kernel(
    const float* __restrict__ tin, const float* __restrict__ g2w,
    const float* __restrict__ b2w, float* __restrict__ out) {
    __shared__ float sred[8];
    int m = blockIdx.x, t = threadIdx.x;
    float2 v = ((const float2*)(tin + (size_t)m * D_MODEL))[t];
    float mu = blockSum256(v.x + v.y, sred) * (1.f / 512.f);
    float dx = v.x - mu, dy = v.y - mu;
    float var = blockSum256(dx * dx + dy * dy, sred) * (1.f / 512.f);
    float rs = rsqrtf(var + 1e-5f);
    int d0 = t * 2;
    int b = m >> 11;
    int s = m & (S_LEN - 1);
    float2 ov = make_float2(dx * rs * g2w[d0] + b2w[d0],
                            dy * rs * g2w[d0 + 1] + b2w[d0 + 1]);
    ((float2*)(out + ((size_t)(s * B_SZ + b)) * D_MODEL))[t] = ov;
}

// ---------------------------------------------------------------------------
// Launch
// ---------------------------------------------------------------------------
#define HSMEM_BN128 (STAGES * (128 + 128) * 64 * 2)   // 98304
#define HSMEM_BN64  (STAGES * (128 + 64) * 64 * 2)    // 73728

extern "C" void kernel_launch(void* const* d_in, const int* in_sizes, int n_in,
                              void* d_out, int out_size) {
    const float* src    = (const float*)d_in[0];
    const float* sph    = (const float*)d_in[1];
    const float* w_qs   = (const float*)d_in[2];
    const float* w_ks   = (const float*)d_in[3];
    const float* w_vs   = (const float*)d_in[4];
    const float* w_fc   = (const float*)d_in[5];
    const float* g_attn = (const float*)d_in[6];
    const float* b_attn = (const float*)d_in[7];
    const float* w1     = (const float*)d_in[8];
    const float* b1     = (const float*)d_in[9];
    const float* w2     = (const float*)d_in[10];
    const float* b2     = (const float*)d_in[11];
    const float* g1w    = (const float*)d_in[12];
    const float* bn1    = (const float*)d_in[13];
    const float* g2w    = (const float*)d_in[14];
    const float* bn2    = (const float*)d_in[15];

    float* out = (float*)d_out;
    float* p_out = out + OUT_ELEMS;

    void* sp = nullptr;
    cudaGetSymbolAddress(&sp, g_scratch);
    float* scr = (float*)sp;
    float* gt1 = scr + OFF_T1;
    float* gh  = scr + OFF_H;
    __half* xh   = (__half*)(scr + OFF_XH);
    __half* qh   = (__half*)(scr + OFF_QH);
    __half* kh   = (__half*)(scr + OFF_KH);
    __half* vt_h = (__half*)(scr + OFF_VTH);
    __half* gaoh = (__half*)(scr + OFF_GAOH);
    __half* hh   = (__half*)(scr + OFF_HH);
    __half* ffh  = (__half*)(scr + OFF_FFH);
    __half* wqh  = (__half*)(scr + OFF_WQH);
    __half* wkh  = (__half*)(scr + OFF_WKH);
    __half* wvh  = (__half*)(scr + OFF_WVH);
    __half* wfch = (__half*)(scr + OFF_WFCH);
    __half* w1h  = (__half*)(scr + OFF_W1H);
    __half* w2h  = (__half*)(scr + OFF_W2H);
    __half* s_h  = (__half*)(scr + OFF_SH);
    float2* part = (float2*)(scr + OFF_PART);

    cudaFuncSetAttribute(gemm_h<0, 128>,
                         cudaFuncAttributeMaxDynamicSharedMemorySize, HSMEM_BN128);
    cudaFuncSetAttribute(gemm_h<4, 64>,
                         cudaFuncAttributeMaxDynamicSharedMemorySize, HSMEM_BN64);
    cudaFuncSetAttribute(gemm_h<5, 128>,
                         cudaFuncAttributeMaxDynamicSharedMemorySize, HSMEM_BN128);
    cudaFuncSetAttribute(gemm_h<6, 64>,
                         cudaFuncAttributeMaxDynamicSharedMemorySize, HSMEM_BN64);

    // 0. fp16 conversions (src perm + all weights)
    convert_all<<<5120, 256>>>(src, w_qs, w_ks, w_vs, w_fc, w1, w2,
                               xh, wqh, wkh, wvh, wfch, w1h, w2h);

    // 1. fused QKV (fp16): z=0 Q, z=1 K, z=2 V^T
    dim3 gqkv(D_MODEL / 128, M_ROWS / 128, 3);
    gemm_h<0, 128><<<gqkv, 256, HSMEM_BN128>>>(
        xh, D_MODEL, wqh, wkh, wvh, D_MODEL, D_MODEL,
        nullptr, nullptr, nullptr, 0, qh);

    // 2. scores = (Q K^T) * 0.125 * sph -> fp16 + softmax partials
    dim3 gsc(S_LEN / 128, S_LEN / 128, B_SZ * H_HEADS);
    scores_f16<<<gsc, 256>>>(qh, kh, sph, s_h, part);

    // 3. fused softmax + PV (no p_h round-trip) -> p_out fp32 + gaoh fp16
    softmax_pv<<<dim3(S_LEN / 64, B_SZ * H_HEADS), 256>>>(s_h, part, vt_h,
                                                          p_out, gaoh);

    // 4. fc projection + residual(src perm) -> gt1 fp32
    dim3 gfc(D_MODEL / 64, M_ROWS / 128, 1);
    gemm_h<4, 64><<<gfc, 256, HSMEM_BN64>>>(
        gaoh, D_MODEL, wfch, nullptr, nullptr, D_MODEL, D_MODEL,
        gt1, nullptr, src, D_MODEL, nullptr);

    // 5. double LayerNorm -> h fp32 + hh fp16
    ln_double_kernel<<<M_ROWS, 256>>>(gt1, src, g_attn, b_attn, g1w, bn1,
                                      gh, hh);

    // 6. FFN up: relu(h @ w1^T + b1) -> ffh fp16
    dim3 gffn(F_FFN / 128, M_ROWS / 128, 1);
    gemm_h<5, 128><<<gffn, 256, HSMEM_BN128>>>(
        hh, D_MODEL, w1h, nullptr, nullptr, D_MODEL, D_MODEL,
        nullptr, b1, nullptr, F_FFN, ffh);

    // 7. FFN down + b2 + residual(h) -> gt1 fp32
    gemm_h<6, 64><<<gfc, 256, HSMEM_BN64>>>(
        ffh, F_FFN, w2h, nullptr, nullptr, F_FFN, F_FFN,
        gt1, b2, gh, D_MODEL, nullptr);

    // 8. final LN + transposed store
    ln_final_kernel<<<M_ROWS, 256>>>(gt1, g2w, bn2, out);
}